// round 1
// baseline (speedup 1.0000x reference)
#include <cuda_runtime.h>
#include <math.h>

// ---------------- constants ----------------
constexpr int B_   = 8;
constexpr int C_   = 2;
constexpr int H_   = 256;
constexpr int W_   = 64;
constexpr int PH_  = 4;
constexpr int PW_  = 4;
constexpr int HP_  = H_ / PH_;   // 64
constexpr int WP_  = W_ / PW_;   // 16
constexpr int N_   = HP_ * WP_;  // 1024
constexpr int HID_ = 1024;
constexpr int NH_  = 16;
constexpr int HD_  = HID_ / NH_; // 64
constexpr int DEPTH_ = 8;
constexpr int FFN_   = 2730;
constexpr int FFNP_  = 2736;     // padded to multiple of 16 floats
constexpr int TDIM_  = 256;
constexpr int OUT_   = PH_ * PW_ * C_; // 32
constexpr int T_     = B_ * N_;        // 8192
constexpr float EPS_ = 1e-6f;

// ---------------- scratch (device globals; no allocs) ----------------
__device__ float g_h   [T_ * HID_];
__device__ float g_hn  [T_ * HID_];
__device__ float g_qkv [T_ * 3 * HID_];
__device__ float g_q   [T_ * HID_];
__device__ float g_k   [T_ * HID_];
__device__ float g_vT  [T_ * HID_];          // [B,NH,HD,N]
__device__ float g_ao  [T_ * HID_];
__device__ float g_S   [B_ * NH_ * N_ * N_]; // 134M floats
__device__ float g_x12 [T_ * 2 * FFN_];
__device__ float g_ffn [T_ * FFNP_];
__device__ float g_w3p [DEPTH_ * HID_ * FFNP_];
__device__ float g_fin [T_ * OUT_];
__device__ float g_cs  [B_ * HID_];
__device__ float g_ada [DEPTH_ * B_ * 6 * HID_];
__device__ float g_fada[B_ * 2 * HID_];

// ---------------- timestep embedding -> c -> silu(c) ----------------
__global__ void k_timestep(const float* __restrict__ t,
                           const float* __restrict__ t_w,
                           const float* __restrict__ t_b)
{
    int b = blockIdx.x;
    int tid = threadIdx.x;
    __shared__ float te[TDIM_];
    float tv = t[b];
    {
        int j = tid & 127;
        float f = __expf(-logf(10000.0f) * (float)j / 128.0f);
        float a = tv * f;
        te[tid] = (tid < 128) ? cosf(a) : sinf(a);
    }
    __syncthreads();
#pragma unroll
    for (int rep = 0; rep < 4; rep++) {
        int o = tid + rep * 256;
        float acc = t_b[o];
        const float* w = t_w + (long long)o * TDIM_;
        for (int j = 0; j < TDIM_; j += 4) {
            float4 wv = *reinterpret_cast<const float4*>(w + j);
            acc += te[j] * wv.x + te[j+1] * wv.y + te[j+2] * wv.z + te[j+3] * wv.w;
        }
        float sig = 1.0f / (1.0f + __expf(-acc));
        g_cs[b * HID_ + o] = acc * sig;
    }
}

// ---------------- all adaLN projections (per-layer ada + final fada) ----------------
__global__ void k_ada(const float* __restrict__ ada_w,
                      const float* __restrict__ ada_b,
                      const float* __restrict__ fada_w,
                      const float* __restrict__ fada_b)
{
    int d = blockIdx.x;            // 0..DEPTH (DEPTH == fada)
    int chunk = blockIdx.y;        // 0..23
    int tid = threadIdx.x;
    __shared__ float css[B_][HID_];
    for (int i = tid; i < B_ * HID_; i += 256)
        css[i >> 10][i & 1023] = g_cs[i];
    __syncthreads();

    int cnt = (d < DEPTH_) ? 6 * HID_ : 2 * HID_;
    int o = chunk * 256 + tid;
    if (o >= cnt) return;

    const float* W = (d < DEPTH_) ? ada_w + ((long long)d * 6 * HID_ + o) * HID_
                                  : fada_w + (long long)o * HID_;
    float bia = (d < DEPTH_) ? ada_b[d * 6 * HID_ + o] : fada_b[o];
    float acc[B_];
#pragma unroll
    for (int b = 0; b < B_; b++) acc[b] = bia;

    for (int j = 0; j < HID_; j += 4) {
        float4 wv = *reinterpret_cast<const float4*>(W + j);
#pragma unroll
        for (int b = 0; b < B_; b++) {
            acc[b] += css[b][j] * wv.x + css[b][j+1] * wv.y
                    + css[b][j+2] * wv.z + css[b][j+3] * wv.w;
        }
    }
#pragma unroll
    for (int b = 0; b < B_; b++) {
        if (d < DEPTH_) g_ada[((long long)(d * B_ + b)) * 6 * HID_ + o] = acc[b];
        else            g_fada[b * 2 * HID_ + o] = acc[b];
    }
}

// ---------------- pad w3 weights to FFNP ----------------
__global__ void k_w3pad(const float* __restrict__ w3_w)
{
    long long idx = (long long)blockIdx.x * 256 + threadIdx.x;
    if (idx >= (long long)DEPTH_ * HID_ * FFNP_) return;
    int j = (int)(idx % FFNP_);
    long long row = idx / FFNP_;   // d*HID + o
    float v = 0.0f;
    if (j < FFN_) v = w3_w[row * FFN_ + j];
    g_w3p[idx] = v;
}

// ---------------- patchify + bias + pos embed ----------------
__global__ void k_patch(const float* __restrict__ x,
                        const float* __restrict__ patch_w,
                        const float* __restrict__ patch_b)
{
    int tok = blockIdx.x;
    int b = tok >> 10;
    int n = tok & 1023;
    int hp = n >> 4;
    int wp = n & 15;
    int tid = threadIdx.x;
    __shared__ float xs[32];
    if (tid < 32) {
        int c = tid >> 4;
        int r = (tid >> 2) & 3;
        int q = tid & 3;
        xs[c * 16 + r * 4 + q] = x[((long long)(b * C_ + c) * H_ + hp * 4 + r) * W_ + wp * 4 + q];
    }
    __syncthreads();
    const float LOG1E4 = logf(10000.0f);
#pragma unroll
    for (int rep = 0; rep < 4; rep++) {
        int o = tid + rep * 256;
        float acc = patch_b[o];
        const float* w = patch_w + o * 32;
#pragma unroll
        for (int i = 0; i < 32; i++) acc += xs[i] * w[i];
        int j = o & 255;
        int sec = o >> 8;
        float omega = __expf(-LOG1E4 * (float)j / 256.0f);
        float p = (sec < 2) ? (float)wp : (float)hp;
        float a = p * omega;
        float pos = (sec & 1) ? cosf(a) : sinf(a);
        g_h[(long long)tok * HID_ + o] = acc + pos;
    }
}

// ---------------- RMSNorm + modulate ----------------
__global__ void k_rmsmod(const float* __restrict__ in, float* __restrict__ out,
                         const float* __restrict__ nw,
                         const float* __restrict__ ada, int ada_stride,
                         int shift_off, int scale_off)
{
    int tok = blockIdx.x;
    int b = tok >> 10;
    int tid = threadIdx.x;
    const float* row = in + (long long)tok * HID_;
    float v[4];
    float s = 0.0f;
#pragma unroll
    for (int i = 0; i < 4; i++) { v[i] = row[tid + i * 256]; s += v[i] * v[i]; }
    __shared__ float red[256];
    red[tid] = s; __syncthreads();
    for (int o = 128; o > 0; o >>= 1) { if (tid < o) red[tid] += red[tid + o]; __syncthreads(); }
    float rs = rsqrtf(red[0] / (float)HID_ + EPS_);
    const float* ar = ada + (long long)b * ada_stride;
    float* orow = out + (long long)tok * HID_;
#pragma unroll
    for (int i = 0; i < 4; i++) {
        int cidx = tid + i * 256;
        orow[cidx] = v[i] * rs * nw[cidx] * (1.0f + ar[scale_off + cidx]) + ar[shift_off + cidx];
    }
}

// ---------------- per-head qk RMSNorm + RoPE + v transpose ----------------
__global__ void k_rope(const float* __restrict__ qn, const float* __restrict__ kn)
{
    int tok = blockIdx.x;
    int b = tok >> 10;
    int n = tok & 1023;
    int tid = threadIdx.x;
    int h = tid >> 4;
    int l = tid & 15;
    int d0 = l * 4;
    const float* row = g_qkv + (long long)tok * 3 * HID_;
    float4 q = *reinterpret_cast<const float4*>(row + h * HD_ + d0);
    float4 k = *reinterpret_cast<const float4*>(row + HID_ + h * HD_ + d0);
    float4 v = *reinterpret_cast<const float4*>(row + 2 * HID_ + h * HD_ + d0);

    float sq = q.x*q.x + q.y*q.y + q.z*q.z + q.w*q.w;
    float sk = k.x*k.x + k.y*k.y + k.z*k.z + k.w*k.w;
#pragma unroll
    for (int o = 1; o < 16; o <<= 1) {
        sq += __shfl_xor_sync(0xffffffffu, sq, o);
        sk += __shfl_xor_sync(0xffffffffu, sk, o);
    }
    float rq = rsqrtf(sq / (float)HD_ + EPS_);
    float rk = rsqrtf(sk / (float)HD_ + EPS_);
    q.x *= rq * qn[d0+0]; q.y *= rq * qn[d0+1]; q.z *= rq * qn[d0+2]; q.w *= rq * qn[d0+3];
    k.x *= rk * kn[d0+0]; k.y *= rk * kn[d0+1]; k.z *= rk * kn[d0+2]; k.w *= rk * kn[d0+3];

    const float LOG1E4 = logf(10000.0f);
    float hpos = (float)(n >> 4);
    float wpos = (float)(n & 15);
#pragma unroll
    for (int pr = 0; pr < 2; pr++) {
        int dp = d0 + pr * 2;
        int jj; float pos;
        if (dp < 32) { jj = dp;      pos = hpos; }
        else         { jj = dp - 32; pos = wpos; }
        float freq = __expf(-LOG1E4 * (float)jj / 32.0f);
        float ang = pos * freq;
        float c = cosf(ang), s = sinf(ang);
        float qx0 = (pr == 0) ? q.x : q.z;
        float qx1 = (pr == 0) ? q.y : q.w;
        float kx0 = (pr == 0) ? k.x : k.z;
        float kx1 = (pr == 0) ? k.y : k.w;
        float qy0 = qx0 * c - qx1 * s;
        float qy1 = qx1 * c + qx0 * s;
        float ky0 = kx0 * c - kx1 * s;
        float ky1 = kx1 * c + kx0 * s;
        if (pr == 0) { q.x = qy0; q.y = qy1; k.x = ky0; k.y = ky1; }
        else         { q.z = qy0; q.w = qy1; k.z = ky0; k.w = ky1; }
    }

    long long qbase = ((long long)(b * NH_ + h) * N_ + n) * HD_ + d0;
    *reinterpret_cast<float4*>(g_q + qbase) = q;
    *reinterpret_cast<float4*>(g_k + qbase) = k;
    long long vb = (long long)(b * NH_ + h) * HD_;
    g_vT[(vb + d0 + 0) * N_ + n] = v.x;
    g_vT[(vb + d0 + 1) * N_ + n] = v.y;
    g_vT[(vb + d0 + 2) * N_ + n] = v.z;
    g_vT[(vb + d0 + 3) * N_ + n] = v.w;
}

// ---------------- row softmax over N ----------------
__global__ void k_softmax()
{
    float* p = g_S + (long long)blockIdx.x * N_;
    int tid = threadIdx.x;
    float v[4];
    float mx = -3.4e38f;
#pragma unroll
    for (int i = 0; i < 4; i++) { v[i] = p[tid + i * 256]; mx = fmaxf(mx, v[i]); }
    __shared__ float red[256];
    red[tid] = mx; __syncthreads();
    for (int o = 128; o > 0; o >>= 1) { if (tid < o) red[tid] = fmaxf(red[tid], red[tid + o]); __syncthreads(); }
    mx = red[0]; __syncthreads();
    float s = 0.0f;
#pragma unroll
    for (int i = 0; i < 4; i++) { v[i] = __expf(v[i] - mx); s += v[i]; }
    red[tid] = s; __syncthreads();
    for (int o = 128; o > 0; o >>= 1) { if (tid < o) red[tid] += red[tid + o]; __syncthreads(); }
    float inv = 1.0f / red[0];
#pragma unroll
    for (int i = 0; i < 4; i++) p[tid + i * 256] = v[i] * inv;
}

// ---------------- SwiGLU: g_ffn = silu(x1)*x2 (padded rows) ----------------
__global__ void k_swiglu()
{
    long long idx = (long long)blockIdx.x * 256 + threadIdx.x;
    if (idx >= (long long)T_ * FFNP_) return;
    int j = (int)(idx % FFNP_);
    long long m = idx / FFNP_;
    float out = 0.0f;
    if (j < FFN_) {
        float a = g_x12[m * (2 * FFN_) + j];
        float b = g_x12[m * (2 * FFN_) + FFN_ + j];
        out = a / (1.0f + __expf(-a)) * b;
    }
    g_ffn[idx] = out;
}

// ---------------- unpatchify ----------------
__global__ void k_unpatch(float* __restrict__ out)
{
    int idx = blockIdx.x * 256 + threadIdx.x;
    if (idx >= B_ * C_ * H_ * W_) return;
    int ww = idx % W_;
    int tmp = idx / W_;
    int hh = tmp % H_;
    int tmp2 = tmp / H_;
    int c = tmp2 % C_;
    int b = tmp2 / C_;
    int hp = hh >> 2, p = hh & 3;
    int wp = ww >> 2, q = ww & 3;
    out[idx] = g_fin[((long long)(b * N_ + hp * WP_ + wp)) * OUT_ + p * (PW_ * C_) + q * C_ + c];
}

// ---------------- generic tiled SGEMM: C = alpha * A @ W^T (+bias)(+gated residual) ----------------
// A: [M,K] lda; W: [Nout,K] ldw; C: [M,Nout-ish] ldc. Batched via grid.z.
__global__ void __launch_bounds__(256, 2)
k_gemm(const float* __restrict__ A, int lda, long long sA,
       const float* __restrict__ Wt, int ldw, long long sW,
       float* __restrict__ Cc, int ldc, long long sC1, long long sC2, int nh,
       int M, int Nout, int K, float alpha,
       const float* __restrict__ bias,
       const float* __restrict__ res,
       const float* __restrict__ gate, int gstride, int mode)
{
    int z = blockIdx.z;
    const float* Ab = A + (long long)z * sA;
    const float* Wb = Wt + (long long)z * sW;
    float* Cb = Cc + (long long)(z / nh) * sC1 + (long long)(z % nh) * sC2;

    int n0 = blockIdx.x * 128;
    int m0 = blockIdx.y * 128;
    int tid = threadIdx.x;
    int lrow = tid >> 1;
    int lcol = (tid & 1) << 2;

    __shared__ float As[8][128];
    __shared__ float Bs[8][128];

    float acc[8][8];
#pragma unroll
    for (int i = 0; i < 8; i++)
#pragma unroll
        for (int j = 0; j < 8; j++) acc[i][j] = 0.0f;

    const float* Ap = Ab + (long long)(m0 + lrow) * lda + lcol;
    int wn = n0 + lrow;
    const float* Wp = Wb + (long long)wn * ldw + lcol;
    bool wvalid = wn < Nout;

    int mbase = (tid >> 4) << 3;
    int nbase = (tid & 15) << 3;

    for (int kt = 0; kt < K; kt += 8) {
        float4 av = *reinterpret_cast<const float4*>(Ap + kt);
        float4 wv = wvalid ? *reinterpret_cast<const float4*>(Wp + kt)
                           : make_float4(0.f, 0.f, 0.f, 0.f);
        __syncthreads();
        As[lcol + 0][lrow] = av.x; As[lcol + 1][lrow] = av.y;
        As[lcol + 2][lrow] = av.z; As[lcol + 3][lrow] = av.w;
        Bs[lcol + 0][lrow] = wv.x; Bs[lcol + 1][lrow] = wv.y;
        Bs[lcol + 2][lrow] = wv.z; Bs[lcol + 3][lrow] = wv.w;
        __syncthreads();
#pragma unroll
        for (int kk = 0; kk < 8; kk++) {
            float a[8], b[8];
#pragma unroll
            for (int i = 0; i < 8; i++) a[i] = As[kk][mbase + i];
#pragma unroll
            for (int j = 0; j < 8; j++) b[j] = Bs[kk][nbase + j];
#pragma unroll
            for (int i = 0; i < 8; i++)
#pragma unroll
                for (int j = 0; j < 8; j++)
                    acc[i][j] = fmaf(a[i], b[j], acc[i][j]);
        }
    }

#pragma unroll
    for (int i = 0; i < 8; i++) {
        int m = m0 + mbase + i;
#pragma unroll
        for (int j = 0; j < 8; j++) {
            int nn = n0 + nbase + j;
            if (nn < Nout) {
                float v = acc[i][j] * alpha;
                if (bias) v += __ldg(bias + nn);
                long long idx = (long long)m * ldc + nn;
                if (mode == 1)
                    v = res[idx] + gate[(m >> 10) * gstride + nn] * v;
                Cb[idx] = v;
            }
        }
    }
}

// ---------------- host orchestration ----------------
extern "C" void kernel_launch(void* const* d_in, const int* in_sizes, int n_in,
                              void* d_out, int out_size)
{
    const float* x       = (const float*)d_in[0];
    const float* t       = (const float*)d_in[1];
    const float* patch_w = (const float*)d_in[2];
    const float* patch_b = (const float*)d_in[3];
    const float* t_w     = (const float*)d_in[4];
    const float* t_b     = (const float*)d_in[5];
    const float* norm1_w = (const float*)d_in[6];
    const float* qkv_w   = (const float*)d_in[7];
    const float* qkv_b   = (const float*)d_in[8];
    const float* qn_w    = (const float*)d_in[9];
    const float* kn_w    = (const float*)d_in[10];
    const float* proj_w  = (const float*)d_in[11];
    const float* proj_b  = (const float*)d_in[12];
    const float* norm2_w = (const float*)d_in[13];
    const float* w12_w   = (const float*)d_in[14];
    const float* w12_b   = (const float*)d_in[15];
    const float* w3_w    = (const float*)d_in[16];
    const float* w3_b    = (const float*)d_in[17];
    const float* ada_w   = (const float*)d_in[18];
    const float* ada_b   = (const float*)d_in[19];
    const float* fnorm_w = (const float*)d_in[20];
    const float* flin_w  = (const float*)d_in[21];
    const float* flin_b  = (const float*)d_in[22];
    const float* fada_w  = (const float*)d_in[23];
    const float* fada_b  = (const float*)d_in[24];
    float* out = (float*)d_out;

    float *p_h, *p_hn, *p_qkv, *p_q, *p_k, *p_vT, *p_ao, *p_S, *p_x12, *p_ffn, *p_w3p, *p_fin, *p_ada, *p_fada;
    cudaGetSymbolAddress((void**)&p_h,   g_h);
    cudaGetSymbolAddress((void**)&p_hn,  g_hn);
    cudaGetSymbolAddress((void**)&p_qkv, g_qkv);
    cudaGetSymbolAddress((void**)&p_q,   g_q);
    cudaGetSymbolAddress((void**)&p_k,   g_k);
    cudaGetSymbolAddress((void**)&p_vT,  g_vT);
    cudaGetSymbolAddress((void**)&p_ao,  g_ao);
    cudaGetSymbolAddress((void**)&p_S,   g_S);
    cudaGetSymbolAddress((void**)&p_x12, g_x12);
    cudaGetSymbolAddress((void**)&p_ffn, g_ffn);
    cudaGetSymbolAddress((void**)&p_w3p, g_w3p);
    cudaGetSymbolAddress((void**)&p_fin, g_fin);
    cudaGetSymbolAddress((void**)&p_ada, g_ada);
    cudaGetSymbolAddress((void**)&p_fada, g_fada);

    auto gemm = [](const float* A, int lda, long long sA,
                   const float* Wt, int ldw, long long sW,
                   float* Cc, int ldc, long long sC1, long long sC2, int nh,
                   int M, int Nout, int K, float alpha,
                   const float* bias, const float* res,
                   const float* gate, int gstride, int mode, int batches) {
        dim3 grid((Nout + 127) / 128, M / 128, batches);
        k_gemm<<<grid, 256>>>(A, lda, sA, Wt, ldw, sW, Cc, ldc, sC1, sC2, nh,
                              M, Nout, K, alpha, bias, res, gate, gstride, mode);
    };

    k_timestep<<<B_, 256>>>(t, t_w, t_b);
    k_ada<<<dim3(DEPTH_ + 1, 24), 256>>>(ada_w, ada_b, fada_w, fada_b);
    {
        long long tot = (long long)DEPTH_ * HID_ * FFNP_;
        k_w3pad<<<(unsigned)((tot + 255) / 256), 256>>>(w3_w);
    }
    k_patch<<<T_, 256>>>(x, patch_w, patch_b);

    for (int d = 0; d < DEPTH_; d++) {
        const float* adab = p_ada + (long long)d * B_ * 6 * HID_;

        // norm1 + modulate(sm, scm)
        k_rmsmod<<<T_, 256>>>(p_h, p_hn, norm1_w + d * HID_, adab, 6 * HID_, 0, HID_);

        // qkv
        gemm(p_hn, HID_, 0,
             qkv_w + (long long)d * 3 * HID_ * HID_, HID_, 0,
             p_qkv, 3 * HID_, 0, 0, 1,
             T_, 3 * HID_, HID_, 1.0f,
             qkv_b + d * 3 * HID_, nullptr, nullptr, 0, 0, 1);

        // qk-norm + rope + v transpose
        k_rope<<<T_, 256>>>(qn_w + d * HD_, kn_w + d * HD_);

        // S = Q K^T * scale   (batched over B*NH)
        gemm(p_q, HD_, (long long)N_ * HD_,
             p_k, HD_, (long long)N_ * HD_,
             p_S, N_, (long long)N_ * N_, 0, 1,
             N_, N_, HD_, 0.125f,
             nullptr, nullptr, nullptr, 0, 0, B_ * NH_);

        k_softmax<<<B_ * NH_ * N_, 256>>>();

        // O = P @ V   (W = V^T), scatter into (B,N,NH,HD)
        gemm(p_S, N_, (long long)N_ * N_,
             p_vT, N_, (long long)HD_ * N_,
             p_ao, HID_, (long long)N_ * HID_, (long long)HD_, NH_,
             N_, HD_, N_, 1.0f,
             nullptr, nullptr, nullptr, 0, 0, B_ * NH_);

        // proj + gated residual (gm)
        gemm(p_ao, HID_, 0,
             proj_w + (long long)d * HID_ * HID_, HID_, 0,
             p_h, HID_, 0, 0, 1,
             T_, HID_, HID_, 1.0f,
             proj_b + d * HID_, p_h, adab + 2 * HID_, 6 * HID_, 1, 1);

        // norm2 + modulate(sp, scp)
        k_rmsmod<<<T_, 256>>>(p_h, p_hn, norm2_w + d * HID_, adab, 6 * HID_, 3 * HID_, 4 * HID_);

        // w12
        gemm(p_hn, HID_, 0,
             w12_w + (long long)d * 2 * FFN_ * HID_, HID_, 0,
             p_x12, 2 * FFN_, 0, 0, 1,
             T_, 2 * FFN_, HID_, 1.0f,
             w12_b + d * 2 * FFN_, nullptr, nullptr, 0, 0, 1);

        // swiglu
        {
            long long tot = (long long)T_ * FFNP_;
            k_swiglu<<<(unsigned)((tot + 255) / 256), 256>>>();
        }

        // w3 + gated residual (gp)
        gemm(p_ffn, FFNP_, 0,
             p_w3p + (long long)d * HID_ * FFNP_, FFNP_, 0,
             p_h, HID_, 0, 0, 1,
             T_, HID_, FFNP_, 1.0f,
             w3_b + d * HID_, p_h, adab + 5 * HID_, 6 * HID_, 1, 1);
    }

    // final norm + modulate(fsh, fsc)
    k_rmsmod<<<T_, 256>>>(p_h, p_hn, fnorm_w, p_fada, 2 * HID_, 0, HID_);

    // final linear
    gemm(p_hn, HID_, 0,
         flin_w, HID_, 0,
         p_fin, OUT_, 0, 0, 1,
         T_, OUT_, HID_, 1.0f,
         flin_b, nullptr, nullptr, 0, 0, 1);

    k_unpatch<<<(B_ * C_ * H_ * W_ + 255) / 256, 256>>>(out);
}

// round 2
// speedup vs baseline: 2.8500x; 2.8500x over previous
#include <cuda_runtime.h>
#include <cuda_bf16.h>
#include <math.h>

// ---------------- constants ----------------
constexpr int B_   = 8;
constexpr int C_   = 2;
constexpr int H_   = 256;
constexpr int W_   = 64;
constexpr int PH_  = 4;
constexpr int PW_  = 4;
constexpr int HP_  = H_ / PH_;   // 64
constexpr int WP_  = W_ / PW_;   // 16
constexpr int N_   = HP_ * WP_;  // 1024
constexpr int HID_ = 1024;
constexpr int NH_  = 16;
constexpr int HD_  = HID_ / NH_; // 64
constexpr int DEPTH_ = 8;
constexpr int FFN_   = 2730;
constexpr int FFNP_  = 2736;     // padded to multiple of 16 floats
constexpr int TDIM_  = 256;
constexpr int OUT_   = PH_ * PW_ * C_; // 32
constexpr int T_     = B_ * N_;        // 8192
constexpr float EPS_ = 1e-6f;

// ---------------- scratch (device globals; no allocs) ----------------
__device__ float g_h   [T_ * HID_];
__device__ float g_hn  [T_ * HID_];
__device__ float g_qkv [T_ * 3 * HID_];
__device__ float g_q   [T_ * HID_];
__device__ float g_k   [T_ * HID_];
__device__ float g_vT  [T_ * HID_];          // [B,NH,HD,N]
__device__ float g_ao  [T_ * HID_];
__device__ float g_S   [B_ * NH_ * N_ * N_]; // 134M floats
__device__ float g_x12 [T_ * 2 * FFN_];
__device__ float g_ffn [T_ * FFNP_];
__device__ float g_w3p [DEPTH_ * HID_ * FFNP_];
__device__ float g_fin [T_ * OUT_];
__device__ float g_cs  [B_ * HID_];
__device__ float g_ada [DEPTH_ * B_ * 6 * HID_];
__device__ float g_fada[B_ * 2 * HID_];

// ---------------- small helpers ----------------
__device__ __forceinline__ unsigned packbf(__nv_bfloat16 a, __nv_bfloat16 b) {
    __nv_bfloat162 t(a, b);
    return *reinterpret_cast<unsigned*>(&t);
}

__device__ __forceinline__ void ldm4(unsigned* r, const unsigned short* p) {
    unsigned addr = (unsigned)__cvta_generic_to_shared(p);
    asm volatile("ldmatrix.sync.aligned.m8n8.x4.shared.b16 {%0,%1,%2,%3}, [%4];"
                 : "=r"(r[0]), "=r"(r[1]), "=r"(r[2]), "=r"(r[3])
                 : "r"(addr));
}

__device__ __forceinline__ void mma16816(float* c, const unsigned* a, const unsigned* b) {
    asm volatile("mma.sync.aligned.m16n8k16.row.col.f32.bf16.bf16.f32 "
                 "{%0,%1,%2,%3},{%4,%5,%6,%7},{%8,%9},{%0,%1,%2,%3};"
                 : "+f"(c[0]), "+f"(c[1]), "+f"(c[2]), "+f"(c[3])
                 : "r"(a[0]), "r"(a[1]), "r"(a[2]), "r"(a[3]),
                   "r"(b[0]), "r"(b[1]));
}

// convert float4 -> (hi,lo) bf16 and store 4 contiguous elements
__device__ __forceinline__ void cvt_store(unsigned short* hiP, unsigned short* loP, float4 v) {
    __nv_bfloat16 h0 = __float2bfloat16(v.x);
    __nv_bfloat16 h1 = __float2bfloat16(v.y);
    __nv_bfloat16 h2 = __float2bfloat16(v.z);
    __nv_bfloat16 h3 = __float2bfloat16(v.w);
    __nv_bfloat16 l0 = __float2bfloat16(v.x - __bfloat162float(h0));
    __nv_bfloat16 l1 = __float2bfloat16(v.y - __bfloat162float(h1));
    __nv_bfloat16 l2 = __float2bfloat16(v.z - __bfloat162float(h2));
    __nv_bfloat16 l3 = __float2bfloat16(v.w - __bfloat162float(h3));
    uint2 hu; hu.x = packbf(h0, h1); hu.y = packbf(h2, h3);
    uint2 lu; lu.x = packbf(l0, l1); lu.y = packbf(l2, l3);
    *reinterpret_cast<uint2*>(hiP) = hu;
    *reinterpret_cast<uint2*>(loP) = lu;
}

// ---------------- bf16-split tensor-core GEMM ----------------
// C = alpha * A @ W^T (+bias)(+gated residual). A:[M,K] lda; W:[Nout,K] ldw.
// Batched via grid.z. 128x128 block tile, BK=16, 3-MMA split compensation.
constexpr int SROW_ = 24;  // smem row stride in bf16 (48B -> conflict-free ldmatrix)

__global__ void __launch_bounds__(256)
k_gemm_bf16(const float* __restrict__ A, int lda, long long sA,
            const float* __restrict__ Wt, int ldw, long long sW,
            float* __restrict__ Cc, int ldc, long long sC1, long long sC2, int nh,
            int M, int Nout, int K, float alpha,
            const float* __restrict__ bias,
            const float* __restrict__ res,
            const float* __restrict__ gate, int gstride, int mode)
{
    __shared__ __align__(16) unsigned short sAm[2][2][128 * SROW_]; // [buf][hi/lo]
    __shared__ __align__(16) unsigned short sBm[2][2][128 * SROW_];

    int z = blockIdx.z;
    const float* Ab = A + (long long)z * sA;
    const float* Wb = Wt + (long long)z * sW;
    float* Cb = Cc + (long long)(z / nh) * sC1 + (long long)(z % nh) * sC2;

    int n0 = blockIdx.x * 128;
    int m0 = blockIdx.y * 128;
    int tid = threadIdx.x;
    int lane = tid & 31;
    int warp = tid >> 5;
    int wm = warp & 3;   // M position (0..3)
    int wn = warp >> 2;  // N position (0..1)

    // staging-load mapping: thread covers rows srow & srow+64, 4 floats at scol
    int srow = tid >> 2;
    int scol = (tid & 3) * 4;

    const float* Ap0 = Ab + (long long)(m0 + srow) * lda + scol;
    const float* Ap1 = Ap0 + (long long)64 * lda;
    int w0 = n0 + srow, w1 = w0 + 64;
    const float* Wp0 = Wb + (long long)w0 * ldw + scol;
    const float* Wp1 = Wb + (long long)w1 * ldw + scol;
    bool v0 = w0 < Nout, v1 = w1 < Nout;

    int st0 = srow * SROW_ + scol;
    int st1 = (srow + 64) * SROW_ + scol;

    // ldmatrix source offsets (in ushort units)
    int aoff[2], boff[4];
#pragma unroll
    for (int mt = 0; mt < 2; mt++)
        aoff[mt] = (wm * 32 + mt * 16 + (lane & 15)) * SROW_ + ((lane >> 4) * 8);
#pragma unroll
    for (int q = 0; q < 4; q++)
        boff[q] = (wn * 64 + q * 16 + (lane & 7) + ((lane >> 4) << 3)) * SROW_
                + (((lane >> 3) & 1) * 8);

    float acc[2][8][4];
#pragma unroll
    for (int mt = 0; mt < 2; mt++)
#pragma unroll
        for (int nt = 0; nt < 8; nt++)
#pragma unroll
            for (int i = 0; i < 4; i++) acc[mt][nt][i] = 0.0f;

    const float4 Z4 = make_float4(0.f, 0.f, 0.f, 0.f);
    float4 ra0, ra1, rb0, rb1;

    // prologue: tile 0
    ra0 = *reinterpret_cast<const float4*>(Ap0);
    ra1 = *reinterpret_cast<const float4*>(Ap1);
    rb0 = v0 ? *reinterpret_cast<const float4*>(Wp0) : Z4;
    rb1 = v1 ? *reinterpret_cast<const float4*>(Wp1) : Z4;
    cvt_store(&sAm[0][0][st0], &sAm[0][1][st0], ra0);
    cvt_store(&sAm[0][0][st1], &sAm[0][1][st1], ra1);
    cvt_store(&sBm[0][0][st0], &sBm[0][1][st0], rb0);
    cvt_store(&sBm[0][0][st1], &sBm[0][1][st1], rb1);

    int ntiles = K / 16;
    int buf = 0;

    for (int t = 1; t <= ntiles; t++) {
        bool more = (t < ntiles);
        if (more) {
            int kt = t * 16;
            ra0 = *reinterpret_cast<const float4*>(Ap0 + kt);
            ra1 = *reinterpret_cast<const float4*>(Ap1 + kt);
            rb0 = v0 ? *reinterpret_cast<const float4*>(Wp0 + kt) : Z4;
            rb1 = v1 ? *reinterpret_cast<const float4*>(Wp1 + kt) : Z4;
        }
        __syncthreads();

        // fragments
        unsigned af[2][2][4];   // [split][mt]
        unsigned bfr[2][8][2];  // [split][nt]
#pragma unroll
        for (int s = 0; s < 2; s++)
#pragma unroll
            for (int mt = 0; mt < 2; mt++)
                ldm4(af[s][mt], &sAm[buf][s][aoff[mt]]);
#pragma unroll
        for (int s = 0; s < 2; s++)
#pragma unroll
            for (int q = 0; q < 4; q++) {
                unsigned r[4];
                ldm4(r, &sBm[buf][s][boff[q]]);
                bfr[s][2 * q][0] = r[0]; bfr[s][2 * q][1] = r[1];
                bfr[s][2 * q + 1][0] = r[2]; bfr[s][2 * q + 1][1] = r[3];
            }
#pragma unroll
        for (int mt = 0; mt < 2; mt++)
#pragma unroll
            for (int nt = 0; nt < 8; nt++) {
                mma16816(acc[mt][nt], af[0][mt], bfr[0][nt]); // hi*hi
                mma16816(acc[mt][nt], af[0][mt], bfr[1][nt]); // hi*lo
                mma16816(acc[mt][nt], af[1][mt], bfr[0][nt]); // lo*hi
            }

        if (more) {
            int nb = buf ^ 1;
            cvt_store(&sAm[nb][0][st0], &sAm[nb][1][st0], ra0);
            cvt_store(&sAm[nb][0][st1], &sAm[nb][1][st1], ra1);
            cvt_store(&sBm[nb][0][st0], &sBm[nb][1][st0], rb0);
            cvt_store(&sBm[nb][0][st1], &sBm[nb][1][st1], rb1);
            buf = nb;
        }
    }

    // epilogue
#pragma unroll
    for (int mt = 0; mt < 2; mt++) {
        int row = m0 + wm * 32 + mt * 16 + (lane >> 2);
#pragma unroll
        for (int nt = 0; nt < 8; nt++) {
            int col = n0 + wn * 64 + nt * 8 + ((lane & 3) << 1);
#pragma unroll
            for (int i = 0; i < 4; i++) {
                int m = row + (i >> 1) * 8;
                int nn = col + (i & 1);
                if (nn < Nout) {
                    float v = acc[mt][nt][i] * alpha;
                    if (bias) v += __ldg(bias + nn);
                    long long idx = (long long)m * ldc + nn;
                    if (mode == 1)
                        v = res[idx] + gate[(m >> 10) * gstride + nn] * v;
                    Cb[idx] = v;
                }
            }
        }
    }
}

// ---------------- timestep embedding -> c -> silu(c) ----------------
__global__ void k_timestep(const float* __restrict__ t,
                           const float* __restrict__ t_w,
                           const float* __restrict__ t_b)
{
    int b = blockIdx.x;
    int tid = threadIdx.x;
    __shared__ float te[TDIM_];
    float tv = t[b];
    {
        int j = tid & 127;
        float f = __expf(-logf(10000.0f) * (float)j / 128.0f);
        float a = tv * f;
        te[tid] = (tid < 128) ? cosf(a) : sinf(a);
    }
    __syncthreads();
#pragma unroll
    for (int rep = 0; rep < 4; rep++) {
        int o = tid + rep * 256;
        float acc = t_b[o];
        const float* w = t_w + (long long)o * TDIM_;
        for (int j = 0; j < TDIM_; j += 4) {
            float4 wv = *reinterpret_cast<const float4*>(w + j);
            acc += te[j] * wv.x + te[j+1] * wv.y + te[j+2] * wv.z + te[j+3] * wv.w;
        }
        float sig = 1.0f / (1.0f + __expf(-acc));
        g_cs[b * HID_ + o] = acc * sig;
    }
}

// ---------------- all adaLN projections ----------------
__global__ void k_ada(const float* __restrict__ ada_w,
                      const float* __restrict__ ada_b,
                      const float* __restrict__ fada_w,
                      const float* __restrict__ fada_b)
{
    int d = blockIdx.x;
    int chunk = blockIdx.y;
    int tid = threadIdx.x;
    __shared__ float css[B_][HID_];
    for (int i = tid; i < B_ * HID_; i += 256)
        css[i >> 10][i & 1023] = g_cs[i];
    __syncthreads();

    int cnt = (d < DEPTH_) ? 6 * HID_ : 2 * HID_;
    int o = chunk * 256 + tid;
    if (o >= cnt) return;

    const float* W = (d < DEPTH_) ? ada_w + ((long long)d * 6 * HID_ + o) * HID_
                                  : fada_w + (long long)o * HID_;
    float bia = (d < DEPTH_) ? ada_b[d * 6 * HID_ + o] : fada_b[o];
    float acc[B_];
#pragma unroll
    for (int b = 0; b < B_; b++) acc[b] = bia;

    for (int j = 0; j < HID_; j += 4) {
        float4 wv = *reinterpret_cast<const float4*>(W + j);
#pragma unroll
        for (int b = 0; b < B_; b++) {
            acc[b] += css[b][j] * wv.x + css[b][j+1] * wv.y
                    + css[b][j+2] * wv.z + css[b][j+3] * wv.w;
        }
    }
#pragma unroll
    for (int b = 0; b < B_; b++) {
        if (d < DEPTH_) g_ada[((long long)(d * B_ + b)) * 6 * HID_ + o] = acc[b];
        else            g_fada[b * 2 * HID_ + o] = acc[b];
    }
}

// ---------------- pad w3 weights to FFNP ----------------
__global__ void k_w3pad(const float* __restrict__ w3_w)
{
    long long idx = (long long)blockIdx.x * 256 + threadIdx.x;
    if (idx >= (long long)DEPTH_ * HID_ * FFNP_) return;
    int j = (int)(idx % FFNP_);
    long long row = idx / FFNP_;
    float v = 0.0f;
    if (j < FFN_) v = w3_w[row * FFN_ + j];
    g_w3p[idx] = v;
}

// ---------------- patchify + bias + pos embed ----------------
__global__ void k_patch(const float* __restrict__ x,
                        const float* __restrict__ patch_w,
                        const float* __restrict__ patch_b)
{
    int tok = blockIdx.x;
    int b = tok >> 10;
    int n = tok & 1023;
    int hp = n >> 4;
    int wp = n & 15;
    int tid = threadIdx.x;
    __shared__ float xs[32];
    if (tid < 32) {
        int c = tid >> 4;
        int r = (tid >> 2) & 3;
        int q = tid & 3;
        xs[c * 16 + r * 4 + q] = x[((long long)(b * C_ + c) * H_ + hp * 4 + r) * W_ + wp * 4 + q];
    }
    __syncthreads();
    const float LOG1E4 = logf(10000.0f);
#pragma unroll
    for (int rep = 0; rep < 4; rep++) {
        int o = tid + rep * 256;
        float acc = patch_b[o];
        const float4* w4 = reinterpret_cast<const float4*>(patch_w + o * 32);
#pragma unroll
        for (int i = 0; i < 8; i++) {
            float4 wv = w4[i];
            acc += xs[i*4+0] * wv.x + xs[i*4+1] * wv.y + xs[i*4+2] * wv.z + xs[i*4+3] * wv.w;
        }
        int j = o & 255;
        int sec = o >> 8;
        float omega = __expf(-LOG1E4 * (float)j / 256.0f);
        float p = (sec < 2) ? (float)wp : (float)hp;
        float a = p * omega;
        float pos = (sec & 1) ? cosf(a) : sinf(a);
        g_h[(long long)tok * HID_ + o] = acc + pos;
    }
}

// ---------------- RMSNorm + modulate ----------------
__global__ void k_rmsmod(const float* __restrict__ in, float* __restrict__ out,
                         const float* __restrict__ nw,
                         const float* __restrict__ ada, int ada_stride,
                         int shift_off, int scale_off)
{
    int tok = blockIdx.x;
    int b = tok >> 10;
    int tid = threadIdx.x;
    const float* row = in + (long long)tok * HID_;
    float v[4];
    float s = 0.0f;
#pragma unroll
    for (int i = 0; i < 4; i++) { v[i] = row[tid + i * 256]; s += v[i] * v[i]; }
    __shared__ float red[256];
    red[tid] = s; __syncthreads();
    for (int o = 128; o > 0; o >>= 1) { if (tid < o) red[tid] += red[tid + o]; __syncthreads(); }
    float rs = rsqrtf(red[0] / (float)HID_ + EPS_);
    const float* ar = ada + (long long)b * ada_stride;
    float* orow = out + (long long)tok * HID_;
#pragma unroll
    for (int i = 0; i < 4; i++) {
        int cidx = tid + i * 256;
        orow[cidx] = v[i] * rs * nw[cidx] * (1.0f + ar[scale_off + cidx]) + ar[shift_off + cidx];
    }
}

// ---------------- per-head qk RMSNorm + RoPE + v transpose ----------------
__global__ void k_rope(const float* __restrict__ qn, const float* __restrict__ kn)
{
    int tok = blockIdx.x;
    int b = tok >> 10;
    int n = tok & 1023;
    int tid = threadIdx.x;
    int h = tid >> 4;
    int l = tid & 15;
    int d0 = l * 4;
    const float* row = g_qkv + (long long)tok * 3 * HID_;
    float4 q = *reinterpret_cast<const float4*>(row + h * HD_ + d0);
    float4 k = *reinterpret_cast<const float4*>(row + HID_ + h * HD_ + d0);
    float4 v = *reinterpret_cast<const float4*>(row + 2 * HID_ + h * HD_ + d0);

    float sq = q.x*q.x + q.y*q.y + q.z*q.z + q.w*q.w;
    float sk = k.x*k.x + k.y*k.y + k.z*k.z + k.w*k.w;
#pragma unroll
    for (int o = 1; o < 16; o <<= 1) {
        sq += __shfl_xor_sync(0xffffffffu, sq, o);
        sk += __shfl_xor_sync(0xffffffffu, sk, o);
    }
    float rq = rsqrtf(sq / (float)HD_ + EPS_);
    float rk = rsqrtf(sk / (float)HD_ + EPS_);
    q.x *= rq * qn[d0+0]; q.y *= rq * qn[d0+1]; q.z *= rq * qn[d0+2]; q.w *= rq * qn[d0+3];
    k.x *= rk * kn[d0+0]; k.y *= rk * kn[d0+1]; k.z *= rk * kn[d0+2]; k.w *= rk * kn[d0+3];

    const float LOG1E4 = logf(10000.0f);
    float hpos = (float)(n >> 4);
    float wpos = (float)(n & 15);
#pragma unroll
    for (int pr = 0; pr < 2; pr++) {
        int dp = d0 + pr * 2;
        int jj; float pos;
        if (dp < 32) { jj = dp;      pos = hpos; }
        else         { jj = dp - 32; pos = wpos; }
        float freq = __expf(-LOG1E4 * (float)jj / 32.0f);
        float ang = pos * freq;
        float c = cosf(ang), s = sinf(ang);
        float qx0 = (pr == 0) ? q.x : q.z;
        float qx1 = (pr == 0) ? q.y : q.w;
        float kx0 = (pr == 0) ? k.x : k.z;
        float kx1 = (pr == 0) ? k.y : k.w;
        float qy0 = qx0 * c - qx1 * s;
        float qy1 = qx1 * c + qx0 * s;
        float ky0 = kx0 * c - kx1 * s;
        float ky1 = kx1 * c + kx0 * s;
        if (pr == 0) { q.x = qy0; q.y = qy1; k.x = ky0; k.y = ky1; }
        else         { q.z = qy0; q.w = qy1; k.z = ky0; k.w = ky1; }
    }

    long long qbase = ((long long)(b * NH_ + h) * N_ + n) * HD_ + d0;
    *reinterpret_cast<float4*>(g_q + qbase) = q;
    *reinterpret_cast<float4*>(g_k + qbase) = k;
    long long vb = (long long)(b * NH_ + h) * HD_;
    g_vT[(vb + d0 + 0) * N_ + n] = v.x;
    g_vT[(vb + d0 + 1) * N_ + n] = v.y;
    g_vT[(vb + d0 + 2) * N_ + n] = v.z;
    g_vT[(vb + d0 + 3) * N_ + n] = v.w;
}

// ---------------- row softmax over N ----------------
__global__ void k_softmax()
{
    float* p = g_S + (long long)blockIdx.x * N_;
    int tid = threadIdx.x;
    float v[4];
    float mx = -3.4e38f;
#pragma unroll
    for (int i = 0; i < 4; i++) { v[i] = p[tid + i * 256]; mx = fmaxf(mx, v[i]); }
    __shared__ float red[256];
    red[tid] = mx; __syncthreads();
    for (int o = 128; o > 0; o >>= 1) { if (tid < o) red[tid] = fmaxf(red[tid], red[tid + o]); __syncthreads(); }
    mx = red[0]; __syncthreads();
    float s = 0.0f;
#pragma unroll
    for (int i = 0; i < 4; i++) { v[i] = __expf(v[i] - mx); s += v[i]; }
    red[tid] = s; __syncthreads();
    for (int o = 128; o > 0; o >>= 1) { if (tid < o) red[tid] += red[tid + o]; __syncthreads(); }
    float inv = 1.0f / red[0];
#pragma unroll
    for (int i = 0; i < 4; i++) p[tid + i * 256] = v[i] * inv;
}

// ---------------- SwiGLU ----------------
__global__ void k_swiglu()
{
    long long idx = (long long)blockIdx.x * 256 + threadIdx.x;
    if (idx >= (long long)T_ * FFNP_) return;
    int j = (int)(idx % FFNP_);
    long long m = idx / FFNP_;
    float out = 0.0f;
    if (j < FFN_) {
        float a = g_x12[m * (2 * FFN_) + j];
        float b = g_x12[m * (2 * FFN_) + FFN_ + j];
        out = a / (1.0f + __expf(-a)) * b;
    }
    g_ffn[idx] = out;
}

// ---------------- unpatchify ----------------
__global__ void k_unpatch(float* __restrict__ out)
{
    int idx = blockIdx.x * 256 + threadIdx.x;
    if (idx >= B_ * C_ * H_ * W_) return;
    int ww = idx % W_;
    int tmp = idx / W_;
    int hh = tmp % H_;
    int tmp2 = tmp / H_;
    int c = tmp2 % C_;
    int b = tmp2 / C_;
    int hp = hh >> 2, p = hh & 3;
    int wp = ww >> 2, q = ww & 3;
    out[idx] = g_fin[((long long)(b * N_ + hp * WP_ + wp)) * OUT_ + p * (PW_ * C_) + q * C_ + c];
}

// ---------------- host orchestration ----------------
extern "C" void kernel_launch(void* const* d_in, const int* in_sizes, int n_in,
                              void* d_out, int out_size)
{
    const float* x       = (const float*)d_in[0];
    const float* t       = (const float*)d_in[1];
    const float* patch_w = (const float*)d_in[2];
    const float* patch_b = (const float*)d_in[3];
    const float* t_w     = (const float*)d_in[4];
    const float* t_b     = (const float*)d_in[5];
    const float* norm1_w = (const float*)d_in[6];
    const float* qkv_w   = (const float*)d_in[7];
    const float* qkv_b   = (const float*)d_in[8];
    const float* qn_w    = (const float*)d_in[9];
    const float* kn_w    = (const float*)d_in[10];
    const float* proj_w  = (const float*)d_in[11];
    const float* proj_b  = (const float*)d_in[12];
    const float* norm2_w = (const float*)d_in[13];
    const float* w12_w   = (const float*)d_in[14];
    const float* w12_b   = (const float*)d_in[15];
    const float* w3_w    = (const float*)d_in[16];
    const float* w3_b    = (const float*)d_in[17];
    const float* ada_w   = (const float*)d_in[18];
    const float* ada_b   = (const float*)d_in[19];
    const float* fnorm_w = (const float*)d_in[20];
    const float* flin_w  = (const float*)d_in[21];
    const float* flin_b  = (const float*)d_in[22];
    const float* fada_w  = (const float*)d_in[23];
    const float* fada_b  = (const float*)d_in[24];
    float* out = (float*)d_out;

    float *p_h, *p_hn, *p_qkv, *p_q, *p_k, *p_vT, *p_ao, *p_S, *p_x12, *p_ffn, *p_w3p, *p_fin, *p_ada, *p_fada;
    cudaGetSymbolAddress((void**)&p_h,   g_h);
    cudaGetSymbolAddress((void**)&p_hn,  g_hn);
    cudaGetSymbolAddress((void**)&p_qkv, g_qkv);
    cudaGetSymbolAddress((void**)&p_q,   g_q);
    cudaGetSymbolAddress((void**)&p_k,   g_k);
    cudaGetSymbolAddress((void**)&p_vT,  g_vT);
    cudaGetSymbolAddress((void**)&p_ao,  g_ao);
    cudaGetSymbolAddress((void**)&p_S,   g_S);
    cudaGetSymbolAddress((void**)&p_x12, g_x12);
    cudaGetSymbolAddress((void**)&p_ffn, g_ffn);
    cudaGetSymbolAddress((void**)&p_w3p, g_w3p);
    cudaGetSymbolAddress((void**)&p_fin, g_fin);
    cudaGetSymbolAddress((void**)&p_ada, g_ada);
    cudaGetSymbolAddress((void**)&p_fada, g_fada);

    auto gemm = [](const float* A, int lda, long long sA,
                   const float* Wt, int ldw, long long sW,
                   float* Cc, int ldc, long long sC1, long long sC2, int nh,
                   int M, int Nout, int K, float alpha,
                   const float* bias, const float* res,
                   const float* gate, int gstride, int mode, int batches) {
        dim3 grid((Nout + 127) / 128, M / 128, batches);
        k_gemm_bf16<<<grid, 256>>>(A, lda, sA, Wt, ldw, sW, Cc, ldc, sC1, sC2, nh,
                                   M, Nout, K, alpha, bias, res, gate, gstride, mode);
    };

    k_timestep<<<B_, 256>>>(t, t_w, t_b);
    k_ada<<<dim3(DEPTH_ + 1, 24), 256>>>(ada_w, ada_b, fada_w, fada_b);
    {
        long long tot = (long long)DEPTH_ * HID_ * FFNP_;
        k_w3pad<<<(unsigned)((tot + 255) / 256), 256>>>(w3_w);
    }
    k_patch<<<T_, 256>>>(x, patch_w, patch_b);

    for (int d = 0; d < DEPTH_; d++) {
        const float* adab = p_ada + (long long)d * B_ * 6 * HID_;

        // norm1 + modulate(sm, scm)
        k_rmsmod<<<T_, 256>>>(p_h, p_hn, norm1_w + d * HID_, adab, 6 * HID_, 0, HID_);

        // qkv
        gemm(p_hn, HID_, 0,
             qkv_w + (long long)d * 3 * HID_ * HID_, HID_, 0,
             p_qkv, 3 * HID_, 0, 0, 1,
             T_, 3 * HID_, HID_, 1.0f,
             qkv_b + d * 3 * HID_, nullptr, nullptr, 0, 0, 1);

        // qk-norm + rope + v transpose
        k_rope<<<T_, 256>>>(qn_w + d * HD_, kn_w + d * HD_);

        // S = Q K^T * scale   (batched over B*NH)
        gemm(p_q, HD_, (long long)N_ * HD_,
             p_k, HD_, (long long)N_ * HD_,
             p_S, N_, (long long)N_ * N_, 0, 1,
             N_, N_, HD_, 0.125f,
             nullptr, nullptr, nullptr, 0, 0, B_ * NH_);

        k_softmax<<<B_ * NH_ * N_, 256>>>();

        // O = P @ V (W = V^T), scatter into (B,N,NH,HD)
        gemm(p_S, N_, (long long)N_ * N_,
             p_vT, N_, (long long)HD_ * N_,
             p_ao, HID_, (long long)N_ * HID_, (long long)HD_, NH_,
             N_, HD_, N_, 1.0f,
             nullptr, nullptr, nullptr, 0, 0, B_ * NH_);

        // proj + gated residual (gm)
        gemm(p_ao, HID_, 0,
             proj_w + (long long)d * HID_ * HID_, HID_, 0,
             p_h, HID_, 0, 0, 1,
             T_, HID_, HID_, 1.0f,
             proj_b + d * HID_, p_h, adab + 2 * HID_, 6 * HID_, 1, 1);

        // norm2 + modulate(sp, scp)
        k_rmsmod<<<T_, 256>>>(p_h, p_hn, norm2_w + d * HID_, adab, 6 * HID_, 3 * HID_, 4 * HID_);

        // w12
        gemm(p_hn, HID_, 0,
             w12_w + (long long)d * 2 * FFN_ * HID_, HID_, 0,
             p_x12, 2 * FFN_, 0, 0, 1,
             T_, 2 * FFN_, HID_, 1.0f,
             w12_b + d * 2 * FFN_, nullptr, nullptr, 0, 0, 1);

        // swiglu
        {
            long long tot = (long long)T_ * FFNP_;
            k_swiglu<<<(unsigned)((tot + 255) / 256), 256>>>();
        }

        // w3 + gated residual (gp)
        gemm(p_ffn, FFNP_, 0,
             p_w3p + (long long)d * HID_ * FFNP_, FFNP_, 0,
             p_h, HID_, 0, 0, 1,
             T_, HID_, FFNP_, 1.0f,
             w3_b + d * HID_, p_h, adab + 5 * HID_, 6 * HID_, 1, 1);
    }

    // final norm + modulate(fsh, fsc)
    k_rmsmod<<<T_, 256>>>(p_h, p_hn, fnorm_w, p_fada, 2 * HID_, 0, HID_);

    // final linear
    gemm(p_hn, HID_, 0,
         flin_w, HID_, 0,
         p_fin, OUT_, 0, 0, 1,
         T_, OUT_, HID_, 1.0f,
         flin_b, nullptr, nullptr, 0, 0, 1);

    k_unpatch<<<(B_ * C_ * H_ * W_ + 255) / 256, 256>>>(out);
}

// round 4
// speedup vs baseline: 3.6421x; 1.2779x over previous
#include <cuda_runtime.h>
#include <cuda_fp16.h>
#include <math.h>

// ---------------- constants ----------------
constexpr int B_   = 8;
constexpr int C_   = 2;
constexpr int H_   = 256;
constexpr int W_   = 64;
constexpr int PH_  = 4;
constexpr int PW_  = 4;
constexpr int HP_  = H_ / PH_;   // 64
constexpr int WP_  = W_ / PW_;   // 16
constexpr int N_   = HP_ * WP_;  // 1024
constexpr int HID_ = 1024;
constexpr int NH_  = 16;
constexpr int HD_  = HID_ / NH_; // 64
constexpr int DEPTH_ = 8;
constexpr int FFN_   = 2730;
constexpr int FFNP_  = 2752;     // padded to multiple of 64
constexpr int TDIM_  = 256;
constexpr int OUT_   = PH_ * PW_ * C_; // 32
constexpr int T_     = B_ * N_;        // 8192
constexpr float EPS_ = 1e-6f;

typedef unsigned short u16;
typedef unsigned int u32;

// ---------------- scratch (device globals; no allocs) ----------------
__device__ float g_h   [T_ * HID_];
__device__ float g_hn  [T_ * HID_];
__device__ float g_qkv [T_ * 3 * HID_];
__device__ float g_q   [T_ * HID_];     // [B*NH][N][HD]
__device__ float g_k   [T_ * HID_];     // [B*NH][N][HD]
__device__ float g_vT  [T_ * HID_];     // [B*NH][HD][N]
__device__ float g_ao  [T_ * HID_];     // [B][N][NH*HD]
__device__ float g_x12 [T_ * 2 * FFN_];
__device__ float g_ffn [T_ * FFNP_];
__device__ float g_fin [T_ * OUT_];
__device__ float g_cs  [B_ * HID_];
__device__ float g_ada [DEPTH_ * B_ * 6 * HID_];
__device__ float g_fada[B_ * 2 * HID_];

// fp16 hi/lo weights (pre-split)
__device__ u16 g_wq_h [DEPTH_ * 3 * HID_ * HID_];
__device__ u16 g_wq_l [DEPTH_ * 3 * HID_ * HID_];
__device__ u16 g_wp_h [DEPTH_ * HID_ * HID_];
__device__ u16 g_wp_l [DEPTH_ * HID_ * HID_];
__device__ u16 g_w12h [DEPTH_ * 2 * FFN_ * HID_];
__device__ u16 g_w12l [DEPTH_ * 2 * FFN_ * HID_];
__device__ u16 g_w3h  [DEPTH_ * HID_ * FFNP_];
__device__ u16 g_w3l  [DEPTH_ * HID_ * FFNP_];
__device__ u16 g_wf_h [OUT_ * HID_];
__device__ u16 g_wf_l [OUT_ * HID_];

// ---------------- helpers ----------------
__device__ __forceinline__ void mmah(float* c, const unsigned* a, const unsigned* b) {
    asm volatile("mma.sync.aligned.m16n8k16.row.col.f32.f16.f16.f32 "
                 "{%0,%1,%2,%3},{%4,%5,%6,%7},{%8,%9},{%0,%1,%2,%3};"
                 : "+f"(c[0]), "+f"(c[1]), "+f"(c[2]), "+f"(c[3])
                 : "r"(a[0]), "r"(a[1]), "r"(a[2]), "r"(a[3]), "r"(b[0]), "r"(b[1]));
}
__device__ __forceinline__ void ldm4(unsigned* r, const u16* p) {
    unsigned addr = (unsigned)__cvta_generic_to_shared(p);
    asm volatile("ldmatrix.sync.aligned.m8n8.x4.shared.b16 {%0,%1,%2,%3}, [%4];"
                 : "=r"(r[0]), "=r"(r[1]), "=r"(r[2]), "=r"(r[3]) : "r"(addr));
}
__device__ __forceinline__ uint2 f4_to_h4(float4 v) {
    __half2 a = __floats2half2_rn(v.x, v.y);
    __half2 b = __floats2half2_rn(v.z, v.w);
    uint2 r; r.x = *reinterpret_cast<u32*>(&a); r.y = *reinterpret_cast<u32*>(&b);
    return r;
}
__device__ __forceinline__ void splith(float v, u16& h, u16& l) {
    __half hb = __float2half_rn(v);
    __half lb = __float2half_rn(v - __half2float(hb));
    h = *reinterpret_cast<u16*>(&hb);
    l = *reinterpret_cast<u16*>(&lb);
}

// ---------------- fp16 2-term GEMM: C = A @ W^T (+bias)(+gated residual) ----------------
// A: fp32 [M,K]; W: pre-split fp16 hi/lo [Nout,K]. 128x128 tile, BK=16, double buffered.
constexpr int SROW_ = 24;

__global__ void __launch_bounds__(256)
k_gemm_h2(const float* __restrict__ A, int lda,
          const u16* __restrict__ Wh, const u16* __restrict__ Wl, int ldw,
          float* __restrict__ C, int ldc,
          int M, int Nout, int K,
          const float* __restrict__ bias,
          const float* __restrict__ res,
          const float* __restrict__ gate, int gstride, int mode)
{
    __shared__ __align__(16) u16 sA [2][128 * SROW_];
    __shared__ __align__(16) u16 sBh[2][128 * SROW_];
    __shared__ __align__(16) u16 sBl[2][128 * SROW_];

    int n0 = blockIdx.x * 128;
    int m0 = blockIdx.y * 128;
    int tid = threadIdx.x;
    int lane = tid & 31;
    int warp = tid >> 5;
    int wm = warp & 3;
    int wn = warp >> 2;

    int srow = tid >> 2;
    int scol = (tid & 3) * 4;

    const float* Ap0 = A + (long long)(m0 + srow) * lda + scol;
    const float* Ap1 = Ap0 + (long long)64 * lda;
    int w0 = n0 + srow, w1 = w0 + 64;
    const u16* Wh0 = Wh + (long long)w0 * ldw + scol;
    const u16* Wh1 = Wh + (long long)w1 * ldw + scol;
    const u16* Wl0 = Wl + (long long)w0 * ldw + scol;
    const u16* Wl1 = Wl + (long long)w1 * ldw + scol;
    bool v0 = w0 < Nout, v1 = w1 < Nout;

    int st0 = srow * SROW_ + scol;
    int st1 = (srow + 64) * SROW_ + scol;

    int aoff[2], boff[4];
#pragma unroll
    for (int mt = 0; mt < 2; mt++)
        aoff[mt] = (wm * 32 + mt * 16 + (lane & 15)) * SROW_ + ((lane >> 4) * 8);
#pragma unroll
    for (int q = 0; q < 4; q++)
        boff[q] = (wn * 64 + q * 16 + (lane & 7) + ((lane >> 4) << 3)) * SROW_
                + (((lane >> 3) & 1) * 8);

    float acc[2][8][4];
#pragma unroll
    for (int mt = 0; mt < 2; mt++)
#pragma unroll
        for (int nt = 0; nt < 8; nt++)
#pragma unroll
            for (int i = 0; i < 4; i++) acc[mt][nt][i] = 0.0f;

    const uint2 Z2 = make_uint2(0u, 0u);
    float4 ra0, ra1;
    uint2 rh0, rh1, rl0, rl1;

    // prologue
    ra0 = *reinterpret_cast<const float4*>(Ap0);
    ra1 = *reinterpret_cast<const float4*>(Ap1);
    rh0 = v0 ? *reinterpret_cast<const uint2*>(Wh0) : Z2;
    rh1 = v1 ? *reinterpret_cast<const uint2*>(Wh1) : Z2;
    rl0 = v0 ? *reinterpret_cast<const uint2*>(Wl0) : Z2;
    rl1 = v1 ? *reinterpret_cast<const uint2*>(Wl1) : Z2;
    *reinterpret_cast<uint2*>(&sA [0][st0]) = f4_to_h4(ra0);
    *reinterpret_cast<uint2*>(&sA [0][st1]) = f4_to_h4(ra1);
    *reinterpret_cast<uint2*>(&sBh[0][st0]) = rh0;
    *reinterpret_cast<uint2*>(&sBh[0][st1]) = rh1;
    *reinterpret_cast<uint2*>(&sBl[0][st0]) = rl0;
    *reinterpret_cast<uint2*>(&sBl[0][st1]) = rl1;

    int ntiles = K / 16;
    int buf = 0;

    for (int t = 1; t <= ntiles; t++) {
        bool more = (t < ntiles);
        if (more) {
            int kt = t * 16;
            ra0 = *reinterpret_cast<const float4*>(Ap0 + kt);
            ra1 = *reinterpret_cast<const float4*>(Ap1 + kt);
            rh0 = v0 ? *reinterpret_cast<const uint2*>(Wh0 + kt) : Z2;
            rh1 = v1 ? *reinterpret_cast<const uint2*>(Wh1 + kt) : Z2;
            rl0 = v0 ? *reinterpret_cast<const uint2*>(Wl0 + kt) : Z2;
            rl1 = v1 ? *reinterpret_cast<const uint2*>(Wl1 + kt) : Z2;
        }
        __syncthreads();

        unsigned af[2][4];
        unsigned bh[8][2], bl[8][2];
#pragma unroll
        for (int mt = 0; mt < 2; mt++)
            ldm4(af[mt], &sA[buf][aoff[mt]]);
#pragma unroll
        for (int q = 0; q < 4; q++) {
            unsigned r[4];
            ldm4(r, &sBh[buf][boff[q]]);
            bh[2*q][0] = r[0]; bh[2*q][1] = r[1];
            bh[2*q+1][0] = r[2]; bh[2*q+1][1] = r[3];
            ldm4(r, &sBl[buf][boff[q]]);
            bl[2*q][0] = r[0]; bl[2*q][1] = r[1];
            bl[2*q+1][0] = r[2]; bl[2*q+1][1] = r[3];
        }
#pragma unroll
        for (int mt = 0; mt < 2; mt++)
#pragma unroll
            for (int nt = 0; nt < 8; nt++) {
                mmah(acc[mt][nt], af[mt], bh[nt]);
                mmah(acc[mt][nt], af[mt], bl[nt]);
            }

        if (more) {
            int nb = buf ^ 1;
            *reinterpret_cast<uint2*>(&sA [nb][st0]) = f4_to_h4(ra0);
            *reinterpret_cast<uint2*>(&sA [nb][st1]) = f4_to_h4(ra1);
            *reinterpret_cast<uint2*>(&sBh[nb][st0]) = rh0;
            *reinterpret_cast<uint2*>(&sBh[nb][st1]) = rh1;
            *reinterpret_cast<uint2*>(&sBl[nb][st0]) = rl0;
            *reinterpret_cast<uint2*>(&sBl[nb][st1]) = rl1;
            buf = nb;
        }
    }

    // epilogue
#pragma unroll
    for (int mt = 0; mt < 2; mt++) {
        int row = m0 + wm * 32 + mt * 16 + (lane >> 2);
#pragma unroll
        for (int nt = 0; nt < 8; nt++) {
            int col = n0 + wn * 64 + nt * 8 + ((lane & 3) << 1);
#pragma unroll
            for (int i = 0; i < 4; i++) {
                int m = row + (i >> 1) * 8;
                int nn = col + (i & 1);
                if (nn < Nout) {
                    float v = acc[mt][nt][i];
                    if (bias) v += __ldg(bias + nn);
                    long long idx = (long long)m * ldc + nn;
                    if (mode == 1)
                        v = res[idx] + gate[(m >> 10) * gstride + nn] * v;
                    C[idx] = v;
                }
            }
        }
    }
}

// ---------------- weight split conversion (fp32 -> fp16 hi/lo, with K padding) ----------------
__global__ void k_wcvth(const float* __restrict__ src, u16* __restrict__ hi, u16* __restrict__ lo,
                        int srcK, int dstK, long long total)
{
    long long i = (long long)blockIdx.x * 256 + threadIdx.x;
    if (i >= total) return;
    int j = (int)(i % dstK);
    long long r = i / dstK;
    float v = (j < srcK) ? src[r * srcK + j] : 0.0f;
    splith(v, hi[i], lo[i]);
}

// ---------------- fused flash attention ----------------
// grid (8 qblocks, B*NH). 256 threads. Q split fp16 2-term, K/V rounded fp16.
constexpr int FST = 72;  // u16 row stride
constexpr int FS_QH = 0;
constexpr int FS_QL = FS_QH + 128 * FST;
constexpr int FS_KH = FS_QL + 128 * FST;
constexpr int FS_VH = FS_KH + 64 * FST;
constexpr int FS_PH = FS_VH + 64 * FST;
constexpr int FS_PL = FS_PH + 128 * FST;
constexpr int FS_U16 = FS_PL + 128 * FST;            // in u16 units
constexpr int FS_SS = 0;                              // float offset after u16 area
constexpr int FS_SC = FS_SS + 128 * 66;
constexpr int FLASH_SMEM = FS_U16 * 2 + (FS_SC + 128) * 4;

__global__ void __launch_bounds__(256)
k_flash(const float* __restrict__ gq, const float* __restrict__ gk,
        const float* __restrict__ gvT, float* __restrict__ gao)
{
    extern __shared__ __align__(16) char fsm[];
    u16* su = reinterpret_cast<u16*>(fsm);
    float* sf = reinterpret_cast<float*>(fsm + FS_U16 * 2);
    u16* sQh = su + FS_QH;
    u16* sQl = su + FS_QL;
    u16* sKh = su + FS_KH;
    u16* sVh = su + FS_VH;
    u16* sPh = su + FS_PH;
    u16* sPl = su + FS_PL;
    float* sS = sf + FS_SS;
    float* sSc = sf + FS_SC;

    int tid = threadIdx.x;
    int lane = tid & 31;
    int warp = tid >> 5;
    int wm = warp & 3;
    int wn = warp >> 2;

    int bh = blockIdx.y;
    int q0 = blockIdx.x * 128;
    const float* Qg = gq + ((long long)bh * N_ + q0) * HD_;
    const float* Kg = gk + (long long)bh * N_ * HD_;
    const float* Vg = gvT + (long long)bh * HD_ * N_;

    // load Q (x 0.125), split fp16 hi/lo
    {
        int r = tid >> 1, c0 = (tid & 1) * 32;
#pragma unroll
        for (int i = 0; i < 8; i++) {
            float4 v = *reinterpret_cast<const float4*>(Qg + (long long)r * HD_ + c0 + i * 4);
            v.x *= 0.125f; v.y *= 0.125f; v.z *= 0.125f; v.w *= 0.125f;
            u16 h[4], l[4];
            splith(v.x, h[0], l[0]); splith(v.y, h[1], l[1]);
            splith(v.z, h[2], l[2]); splith(v.w, h[3], l[3]);
            *reinterpret_cast<uint2*>(&sQh[r * FST + c0 + i * 4]) = *reinterpret_cast<uint2*>(h);
            *reinterpret_cast<uint2*>(&sQl[r * FST + c0 + i * 4]) = *reinterpret_cast<uint2*>(l);
        }
    }
    // load K,V chunk 0
    {
        int r = tid >> 2, fc = tid & 3;
#pragma unroll
        for (int i = 0; i < 4; i++) {
            int c = (fc * 4 + i) * 4;
            float4 kv = *reinterpret_cast<const float4*>(Kg + (long long)r * HD_ + c);
            float4 vv = *reinterpret_cast<const float4*>(Vg + (long long)r * N_ + c);
            *reinterpret_cast<uint2*>(&sKh[r * FST + c]) = f4_to_h4(kv);
            *reinterpret_cast<uint2*>(&sVh[r * FST + c]) = f4_to_h4(vv);
        }
    }
    __syncthreads();

    float m_st = -1e30f, l_st = 0.0f;
    float o[2][4][4];
#pragma unroll
    for (int mt = 0; mt < 2; mt++)
#pragma unroll
        for (int nt = 0; nt < 4; nt++)
#pragma unroll
            for (int i = 0; i < 4; i++) o[mt][nt][i] = 0.0f;

    int aoffA[2], boffB[2];
#pragma unroll
    for (int mt = 0; mt < 2; mt++)
        aoffA[mt] = (wm * 32 + mt * 16 + (lane & 15)) * FST + ((lane >> 4) * 8);
#pragma unroll
    for (int g = 0; g < 2; g++)
        boffB[g] = (wn * 32 + g * 16 + (lane & 7) + ((lane >> 4) << 3)) * FST
                 + (((lane >> 3) & 1) * 8);

    for (int c = 0; c < 16; c++) {
        // prefetch next K/V chunk
        float4 pk[4], pv[4];
        if (c < 15) {
            int r = tid >> 2, fc = tid & 3;
            long long kbase = (long long)(c + 1) * 64;
#pragma unroll
            for (int i = 0; i < 4; i++) {
                int cc = (fc * 4 + i) * 4;
                pk[i] = *reinterpret_cast<const float4*>(Kg + (kbase + r) * HD_ + cc);
                pv[i] = *reinterpret_cast<const float4*>(Vg + (long long)r * N_ + kbase + cc);
            }
        }

        // MMA1: S = (Qh + Ql) @ K^T
        float s[2][4][4];
#pragma unroll
        for (int mt = 0; mt < 2; mt++)
#pragma unroll
            for (int nt = 0; nt < 4; nt++)
#pragma unroll
                for (int i = 0; i < 4; i++) s[mt][nt][i] = 0.0f;
#pragma unroll
        for (int ks = 0; ks < 4; ks++) {
            unsigned ah[2][4], al[2][4], bk[4][2];
#pragma unroll
            for (int mt = 0; mt < 2; mt++) {
                ldm4(ah[mt], &sQh[aoffA[mt] + ks * 16]);
                ldm4(al[mt], &sQl[aoffA[mt] + ks * 16]);
            }
#pragma unroll
            for (int g = 0; g < 2; g++) {
                unsigned r[4];
                ldm4(r, &sKh[boffB[g] + ks * 16]);
                bk[2*g][0] = r[0]; bk[2*g][1] = r[1];
                bk[2*g+1][0] = r[2]; bk[2*g+1][1] = r[3];
            }
#pragma unroll
            for (int mt = 0; mt < 2; mt++)
#pragma unroll
                for (int nt = 0; nt < 4; nt++) {
                    mmah(s[mt][nt], ah[mt], bk[nt]);
                    mmah(s[mt][nt], al[mt], bk[nt]);
                }
        }
        // write S to smem
#pragma unroll
        for (int mt = 0; mt < 2; mt++) {
            int r0 = wm * 32 + mt * 16 + (lane >> 2);
#pragma unroll
            for (int nt = 0; nt < 4; nt++) {
                int col = wn * 32 + nt * 8 + (lane & 3) * 2;
                *reinterpret_cast<float2*>(&sS[r0 * 66 + col]) = make_float2(s[mt][nt][0], s[mt][nt][1]);
                *reinterpret_cast<float2*>(&sS[(r0 + 8) * 66 + col]) = make_float2(s[mt][nt][2], s[mt][nt][3]);
            }
        }
        __syncthreads();

        // online softmax (rows owned by tid<128)
        if (tid < 128) {
            const float* row = sS + tid * 66;
            float mx = m_st;
#pragma unroll
            for (int j = 0; j < 64; j++) mx = fmaxf(mx, row[j]);
            float corr = __expf(m_st - mx);
            float sum = 0.0f;
#pragma unroll
            for (int j0 = 0; j0 < 64; j0 += 4) {
                float p0 = __expf(row[j0+0] - mx);
                float p1 = __expf(row[j0+1] - mx);
                float p2 = __expf(row[j0+2] - mx);
                float p3 = __expf(row[j0+3] - mx);
                sum += (p0 + p1) + (p2 + p3);
                u16 h[4], l[4];
                splith(p0, h[0], l[0]); splith(p1, h[1], l[1]);
                splith(p2, h[2], l[2]); splith(p3, h[3], l[3]);
                *reinterpret_cast<uint2*>(&sPh[tid * FST + j0]) = *reinterpret_cast<uint2*>(h);
                *reinterpret_cast<uint2*>(&sPl[tid * FST + j0]) = *reinterpret_cast<uint2*>(l);
            }
            l_st = l_st * corr + sum;
            m_st = mx;
            sSc[tid] = corr;
        }
        __syncthreads();

        // rescale O and MMA2: O += (Ph + Pl) @ V^T
#pragma unroll
        for (int mt = 0; mt < 2; mt++) {
            int r0 = wm * 32 + mt * 16 + (lane >> 2);
            float f0 = sSc[r0], f1 = sSc[r0 + 8];
#pragma unroll
            for (int nt = 0; nt < 4; nt++) {
                o[mt][nt][0] *= f0; o[mt][nt][1] *= f0;
                o[mt][nt][2] *= f1; o[mt][nt][3] *= f1;
            }
        }
#pragma unroll
        for (int ks = 0; ks < 4; ks++) {
            unsigned ah[2][4], al[2][4], bv[4][2];
#pragma unroll
            for (int mt = 0; mt < 2; mt++) {
                ldm4(ah[mt], &sPh[aoffA[mt] + ks * 16]);
                ldm4(al[mt], &sPl[aoffA[mt] + ks * 16]);
            }
#pragma unroll
            for (int g = 0; g < 2; g++) {
                unsigned r[4];
                ldm4(r, &sVh[boffB[g] + ks * 16]);
                bv[2*g][0] = r[0]; bv[2*g][1] = r[1];
                bv[2*g+1][0] = r[2]; bv[2*g+1][1] = r[3];
            }
#pragma unroll
            for (int mt = 0; mt < 2; mt++)
#pragma unroll
                for (int nt = 0; nt < 4; nt++) {
                    mmah(o[mt][nt], ah[mt], bv[nt]);
                    mmah(o[mt][nt], al[mt], bv[nt]);
                }
        }
        __syncthreads();

        // commit prefetched K/V
        if (c < 15) {
            int r = tid >> 2, fc = tid & 3;
#pragma unroll
            for (int i = 0; i < 4; i++) {
                int cc = (fc * 4 + i) * 4;
                *reinterpret_cast<uint2*>(&sKh[r * FST + cc]) = f4_to_h4(pk[i]);
                *reinterpret_cast<uint2*>(&sVh[r * FST + cc]) = f4_to_h4(pv[i]);
            }
        }
        __syncthreads();
    }

    // final 1/l
    if (tid < 128) sSc[tid] = 1.0f / l_st;
    __syncthreads();

    int bb = bh >> 4, hh = bh & 15;
#pragma unroll
    for (int mt = 0; mt < 2; mt++) {
        int lr = wm * 32 + mt * 16 + (lane >> 2);
        float f0 = sSc[lr], f1 = sSc[lr + 8];
        int r0 = q0 + lr;
#pragma unroll
        for (int nt = 0; nt < 4; nt++) {
            int col = wn * 32 + nt * 8 + (lane & 3) * 2;
            long long a0 = ((long long)(bb * N_ + r0) * NH_ + hh) * HD_ + col;
            long long a1 = ((long long)(bb * N_ + r0 + 8) * NH_ + hh) * HD_ + col;
            *reinterpret_cast<float2*>(gao + a0) = make_float2(o[mt][nt][0] * f0, o[mt][nt][1] * f0);
            *reinterpret_cast<float2*>(gao + a1) = make_float2(o[mt][nt][2] * f1, o[mt][nt][3] * f1);
        }
    }
}

// ---------------- timestep embedding -> c -> silu(c) ----------------
__global__ void k_timestep(const float* __restrict__ t,
                           const float* __restrict__ t_w,
                           const float* __restrict__ t_b)
{
    int b = blockIdx.x;
    int tid = threadIdx.x;
    __shared__ float te[TDIM_];
    float tv = t[b];
    {
        int j = tid & 127;
        float f = __expf(-logf(10000.0f) * (float)j / 128.0f);
        float a = tv * f;
        te[tid] = (tid < 128) ? cosf(a) : sinf(a);
    }
    __syncthreads();
#pragma unroll
    for (int rep = 0; rep < 4; rep++) {
        int o = tid + rep * 256;
        float acc = t_b[o];
        const float* w = t_w + (long long)o * TDIM_;
        for (int j = 0; j < TDIM_; j += 4) {
            float4 wv = *reinterpret_cast<const float4*>(w + j);
            acc += te[j] * wv.x + te[j+1] * wv.y + te[j+2] * wv.z + te[j+3] * wv.w;
        }
        float sig = 1.0f / (1.0f + __expf(-acc));
        g_cs[b * HID_ + o] = acc * sig;
    }
}

// ---------------- all adaLN projections ----------------
__global__ void k_ada(const float* __restrict__ ada_w,
                      const float* __restrict__ ada_b,
                      const float* __restrict__ fada_w,
                      const float* __restrict__ fada_b)
{
    int d = blockIdx.x;
    int chunk = blockIdx.y;
    int tid = threadIdx.x;
    __shared__ float css[B_][HID_];
    for (int i = tid; i < B_ * HID_; i += 256)
        css[i >> 10][i & 1023] = g_cs[i];
    __syncthreads();

    int cnt = (d < DEPTH_) ? 6 * HID_ : 2 * HID_;
    int o = chunk * 256 + tid;
    if (o >= cnt) return;

    const float* W = (d < DEPTH_) ? ada_w + ((long long)d * 6 * HID_ + o) * HID_
                                  : fada_w + (long long)o * HID_;
    float bia = (d < DEPTH_) ? ada_b[d * 6 * HID_ + o] : fada_b[o];
    float acc[B_];
#pragma unroll
    for (int b = 0; b < B_; b++) acc[b] = bia;

    for (int j = 0; j < HID_; j += 4) {
        float4 wv = *reinterpret_cast<const float4*>(W + j);
#pragma unroll
        for (int b = 0; b < B_; b++) {
            acc[b] += css[b][j] * wv.x + css[b][j+1] * wv.y
                    + css[b][j+2] * wv.z + css[b][j+3] * wv.w;
        }
    }
#pragma unroll
    for (int b = 0; b < B_; b++) {
        if (d < DEPTH_) g_ada[((long long)(d * B_ + b)) * 6 * HID_ + o] = acc[b];
        else            g_fada[b * 2 * HID_ + o] = acc[b];
    }
}

// ---------------- patchify + bias + pos embed ----------------
__global__ void k_patch(const float* __restrict__ x,
                        const float* __restrict__ patch_w,
                        const float* __restrict__ patch_b)
{
    int tok = blockIdx.x;
    int b = tok >> 10;
    int n = tok & 1023;
    int hp = n >> 4;
    int wp = n & 15;
    int tid = threadIdx.x;
    __shared__ float xs[32];
    if (tid < 32) {
        int c = tid >> 4;
        int r = (tid >> 2) & 3;
        int q = tid & 3;
        xs[c * 16 + r * 4 + q] = x[((long long)(b * C_ + c) * H_ + hp * 4 + r) * W_ + wp * 4 + q];
    }
    __syncthreads();
    const float LOG1E4 = logf(10000.0f);
#pragma unroll
    for (int rep = 0; rep < 4; rep++) {
        int o = tid + rep * 256;
        float acc = patch_b[o];
        const float4* w4 = reinterpret_cast<const float4*>(patch_w + o * 32);
#pragma unroll
        for (int i = 0; i < 8; i++) {
            float4 wv = w4[i];
            acc += xs[i*4+0] * wv.x + xs[i*4+1] * wv.y + xs[i*4+2] * wv.z + xs[i*4+3] * wv.w;
        }
        int j = o & 255;
        int sec = o >> 8;
        float omega = __expf(-LOG1E4 * (float)j / 256.0f);
        float p = (sec < 2) ? (float)wp : (float)hp;
        float a = p * omega;
        float pos = (sec & 1) ? cosf(a) : sinf(a);
        g_h[(long long)tok * HID_ + o] = acc + pos;
    }
}

// ---------------- RMSNorm + modulate (fp32 out) ----------------
__global__ void k_rmsmod(const float* __restrict__ in, float* __restrict__ out,
                         const float* __restrict__ nw,
                         const float* __restrict__ ada, int ada_stride,
                         int shift_off, int scale_off)
{
    int tok = blockIdx.x;
    int b = tok >> 10;
    int tid = threadIdx.x;
    const float* row = in + (long long)tok * HID_;
    float v[4];
    float s = 0.0f;
#pragma unroll
    for (int i = 0; i < 4; i++) { v[i] = row[tid + i * 256]; s += v[i] * v[i]; }
    __shared__ float red[256];
    red[tid] = s; __syncthreads();
    for (int o = 128; o > 0; o >>= 1) { if (tid < o) red[tid] += red[tid + o]; __syncthreads(); }
    float rs = rsqrtf(red[0] / (float)HID_ + EPS_);
    const float* ar = ada + (long long)b * ada_stride;
    float* orow = out + (long long)tok * HID_;
#pragma unroll
    for (int i = 0; i < 4; i++) {
        int cidx = tid + i * 256;
        orow[cidx] = v[i] * rs * nw[cidx] * (1.0f + ar[scale_off + cidx]) + ar[shift_off + cidx];
    }
}

// ---------------- per-head qk RMSNorm + RoPE + v transpose ----------------
__global__ void k_rope(const float* __restrict__ qn, const float* __restrict__ kn)
{
    int tok = blockIdx.x;
    int b = tok >> 10;
    int n = tok & 1023;
    int tid = threadIdx.x;
    int h = tid >> 4;
    int l = tid & 15;
    int d0 = l * 4;
    const float* row = g_qkv + (long long)tok * 3 * HID_;
    float4 q = *reinterpret_cast<const float4*>(row + h * HD_ + d0);
    float4 k = *reinterpret_cast<const float4*>(row + HID_ + h * HD_ + d0);
    float4 v = *reinterpret_cast<const float4*>(row + 2 * HID_ + h * HD_ + d0);

    float sq = q.x*q.x + q.y*q.y + q.z*q.z + q.w*q.w;
    float sk = k.x*k.x + k.y*k.y + k.z*k.z + k.w*k.w;
#pragma unroll
    for (int o = 1; o < 16; o <<= 1) {
        sq += __shfl_xor_sync(0xffffffffu, sq, o);
        sk += __shfl_xor_sync(0xffffffffu, sk, o);
    }
    float rq = rsqrtf(sq / (float)HD_ + EPS_);
    float rk = rsqrtf(sk / (float)HD_ + EPS_);
    q.x *= rq * qn[d0+0]; q.y *= rq * qn[d0+1]; q.z *= rq * qn[d0+2]; q.w *= rq * qn[d0+3];
    k.x *= rk * kn[d0+0]; k.y *= rk * kn[d0+1]; k.z *= rk * kn[d0+2]; k.w *= rk * kn[d0+3];

    const float LOG1E4 = logf(10000.0f);
    float hpos = (float)(n >> 4);
    float wpos = (float)(n & 15);
#pragma unroll
    for (int pr = 0; pr < 2; pr++) {
        int dp = d0 + pr * 2;
        int jj; float pos;
        if (dp < 32) { jj = dp;      pos = hpos; }
        else         { jj = dp - 32; pos = wpos; }
        float freq = __expf(-LOG1E4 * (float)jj / 32.0f);
        float ang = pos * freq;
        float c = cosf(ang), s = sinf(ang);
        float qx0 = (pr == 0) ? q.x : q.z;
        float qx1 = (pr == 0) ? q.y : q.w;
        float kx0 = (pr == 0) ? k.x : k.z;
        float kx1 = (pr == 0) ? k.y : k.w;
        float qy0 = qx0 * c - qx1 * s;
        float qy1 = qx1 * c + qx0 * s;
        float ky0 = kx0 * c - kx1 * s;
        float ky1 = kx1 * c + kx0 * s;
        if (pr == 0) { q.x = qy0; q.y = qy1; k.x = ky0; k.y = ky1; }
        else         { q.z = qy0; q.w = qy1; k.z = ky0; k.w = ky1; }
    }

    long long qbase = ((long long)(b * NH_ + h) * N_ + n) * HD_ + d0;
    *reinterpret_cast<float4*>(g_q + qbase) = q;
    *reinterpret_cast<float4*>(g_k + qbase) = k;
    long long vb = (long long)(b * NH_ + h) * HD_;
    g_vT[(vb + d0 + 0) * N_ + n] = v.x;
    g_vT[(vb + d0 + 1) * N_ + n] = v.y;
    g_vT[(vb + d0 + 2) * N_ + n] = v.z;
    g_vT[(vb + d0 + 3) * N_ + n] = v.w;
}

// ---------------- SwiGLU (fp32 out, padded) ----------------
__global__ void k_swiglu()
{
    long long idx = (long long)blockIdx.x * 256 + threadIdx.x;
    if (idx >= (long long)T_ * FFNP_) return;
    int j = (int)(idx % FFNP_);
    long long m = idx / FFNP_;
    float out = 0.0f;
    if (j < FFN_) {
        float a = g_x12[m * (2 * FFN_) + j];
        float b = g_x12[m * (2 * FFN_) + FFN_ + j];
        out = a / (1.0f + __expf(-a)) * b;
    }
    g_ffn[idx] = out;
}

// ---------------- unpatchify ----------------
__global__ void k_unpatch(float* __restrict__ out)
{
    int idx = blockIdx.x * 256 + threadIdx.x;
    if (idx >= B_ * C_ * H_ * W_) return;
    int ww = idx % W_;
    int tmp = idx / W_;
    int hh = tmp % H_;
    int tmp2 = tmp / H_;
    int c = tmp2 % C_;
    int b = tmp2 / C_;
    int hp = hh >> 2, p = hh & 3;
    int wp = ww >> 2, q = ww & 3;
    out[idx] = g_fin[((long long)(b * N_ + hp * WP_ + wp)) * OUT_ + p * (PW_ * C_) + q * C_ + c];
}

// ---------------- host orchestration ----------------
extern "C" void kernel_launch(void* const* d_in, const int* in_sizes, int n_in,
                              void* d_out, int out_size)
{
    const float* x       = (const float*)d_in[0];
    const float* t       = (const float*)d_in[1];
    const float* patch_w = (const float*)d_in[2];
    const float* patch_b = (const float*)d_in[3];
    const float* t_w     = (const float*)d_in[4];
    const float* t_b     = (const float*)d_in[5];
    const float* norm1_w = (const float*)d_in[6];
    const float* qkv_w   = (const float*)d_in[7];
    const float* qkv_b   = (const float*)d_in[8];
    const float* qn_w    = (const float*)d_in[9];
    const float* kn_w    = (const float*)d_in[10];
    const float* proj_w  = (const float*)d_in[11];
    const float* proj_b  = (const float*)d_in[12];
    const float* norm2_w = (const float*)d_in[13];
    const float* w12_w   = (const float*)d_in[14];
    const float* w12_b   = (const float*)d_in[15];
    const float* w3_w    = (const float*)d_in[16];
    const float* w3_b    = (const float*)d_in[17];
    const float* ada_w   = (const float*)d_in[18];
    const float* ada_b   = (const float*)d_in[19];
    const float* fnorm_w = (const float*)d_in[20];
    const float* flin_w  = (const float*)d_in[21];
    const float* flin_b  = (const float*)d_in[22];
    const float* fada_w  = (const float*)d_in[23];
    const float* fada_b  = (const float*)d_in[24];
    float* out = (float*)d_out;

    cudaFuncSetAttribute(k_flash, cudaFuncAttributeMaxDynamicSharedMemorySize, FLASH_SMEM);

    float *p_h, *p_hn, *p_qkv, *p_q, *p_k, *p_vT, *p_ao, *p_x12, *p_ffn, *p_fin, *p_ada, *p_fada;
    u16 *p_wqh, *p_wql, *p_wph, *p_wpl, *p_w12h, *p_w12l, *p_w3h, *p_w3l, *p_wfh, *p_wfl;
    cudaGetSymbolAddress((void**)&p_h,   g_h);
    cudaGetSymbolAddress((void**)&p_hn,  g_hn);
    cudaGetSymbolAddress((void**)&p_qkv, g_qkv);
    cudaGetSymbolAddress((void**)&p_q,   g_q);
    cudaGetSymbolAddress((void**)&p_k,   g_k);
    cudaGetSymbolAddress((void**)&p_vT,  g_vT);
    cudaGetSymbolAddress((void**)&p_ao,  g_ao);
    cudaGetSymbolAddress((void**)&p_x12, g_x12);
    cudaGetSymbolAddress((void**)&p_ffn, g_ffn);
    cudaGetSymbolAddress((void**)&p_fin, g_fin);
    cudaGetSymbolAddress((void**)&p_ada, g_ada);
    cudaGetSymbolAddress((void**)&p_fada, g_fada);
    cudaGetSymbolAddress((void**)&p_wqh, g_wq_h);
    cudaGetSymbolAddress((void**)&p_wql, g_wq_l);
    cudaGetSymbolAddress((void**)&p_wph, g_wp_h);
    cudaGetSymbolAddress((void**)&p_wpl, g_wp_l);
    cudaGetSymbolAddress((void**)&p_w12h, g_w12h);
    cudaGetSymbolAddress((void**)&p_w12l, g_w12l);
    cudaGetSymbolAddress((void**)&p_w3h, g_w3h);
    cudaGetSymbolAddress((void**)&p_w3l, g_w3l);
    cudaGetSymbolAddress((void**)&p_wfh, g_wf_h);
    cudaGetSymbolAddress((void**)&p_wfl, g_wf_l);

    auto cvt = [](const float* src, u16* hi, u16* lo, int srcK, int dstK, long long rows) {
        long long total = rows * dstK;
        k_wcvth<<<(unsigned)((total + 255) / 256), 256>>>(src, hi, lo, srcK, dstK, total);
    };

    auto gemm = [](const float* A, int lda, const u16* Wh, const u16* Wl, int ldw,
                   float* C, int ldc, int M, int Nout, int K,
                   const float* bias, const float* res,
                   const float* gate, int gstride, int mode) {
        dim3 grid((Nout + 127) / 128, M / 128);
        k_gemm_h2<<<grid, 256>>>(A, lda, Wh, Wl, ldw, C, ldc, M, Nout, K,
                                 bias, res, gate, gstride, mode);
    };

    // setup
    k_timestep<<<B_, 256>>>(t, t_w, t_b);
    k_ada<<<dim3(DEPTH_ + 1, 24), 256>>>(ada_w, ada_b, fada_w, fada_b);
    cvt(qkv_w, p_wqh, p_wql, HID_, HID_, (long long)DEPTH_ * 3 * HID_);
    cvt(proj_w, p_wph, p_wpl, HID_, HID_, (long long)DEPTH_ * HID_);
    cvt(w12_w, p_w12h, p_w12l, HID_, HID_, (long long)DEPTH_ * 2 * FFN_);
    cvt(w3_w, p_w3h, p_w3l, FFN_, FFNP_, (long long)DEPTH_ * HID_);
    cvt(flin_w, p_wfh, p_wfl, HID_, HID_, OUT_);
    k_patch<<<T_, 256>>>(x, patch_w, patch_b);

    for (int d = 0; d < DEPTH_; d++) {
        const float* adab = p_ada + (long long)d * B_ * 6 * HID_;

        // norm1 + modulate
        k_rmsmod<<<T_, 256>>>(p_h, p_hn, norm1_w + d * HID_, adab, 6 * HID_, 0, HID_);

        // qkv
        gemm(p_hn, HID_, p_wqh + (long long)d * 3 * HID_ * HID_,
             p_wql + (long long)d * 3 * HID_ * HID_, HID_,
             p_qkv, 3 * HID_, T_, 3 * HID_, HID_,
             qkv_b + d * 3 * HID_, nullptr, nullptr, 0, 0);

        // qk-norm + rope + v transpose
        k_rope<<<T_, 256>>>(qn_w + d * HD_, kn_w + d * HD_);

        // fused flash attention -> g_ao
        k_flash<<<dim3(N_ / 128, B_ * NH_), 256, FLASH_SMEM>>>(p_q, p_k, p_vT, p_ao);

        // proj + gated residual (gm)
        gemm(p_ao, HID_, p_wph + (long long)d * HID_ * HID_,
             p_wpl + (long long)d * HID_ * HID_, HID_,
             p_h, HID_, T_, HID_, HID_,
             proj_b + d * HID_, p_h, adab + 2 * HID_, 6 * HID_, 1);

        // norm2 + modulate
        k_rmsmod<<<T_, 256>>>(p_h, p_hn, norm2_w + d * HID_, adab, 6 * HID_, 3 * HID_, 4 * HID_);

        // w12
        gemm(p_hn, HID_, p_w12h + (long long)d * 2 * FFN_ * HID_,
             p_w12l + (long long)d * 2 * FFN_ * HID_, HID_,
             p_x12, 2 * FFN_, T_, 2 * FFN_, HID_,
             w12_b + d * 2 * FFN_, nullptr, nullptr, 0, 0);

        // swiglu
        {
            long long tot = (long long)T_ * FFNP_;
            k_swiglu<<<(unsigned)((tot + 255) / 256), 256>>>();
        }

        // w3 + gated residual (gp)
        gemm(p_ffn, FFNP_, p_w3h + (long long)d * HID_ * FFNP_,
             p_w3l + (long long)d * HID_ * FFNP_, FFNP_,
             p_h, HID_, T_, HID_, FFNP_,
             w3_b + d * HID_, p_h, adab + 5 * HID_, 6 * HID_, 1);
    }

    // final norm + modulate
    k_rmsmod<<<T_, 256>>>(p_h, p_hn, fnorm_w, p_fada, 2 * HID_, 0, HID_);

    // final linear
    gemm(p_hn, HID_, p_wfh, p_wfl, HID_,
         p_fin, OUT_, T_, OUT_, HID_,
         flin_b, nullptr, nullptr, 0, 0);

    k_unpatch<<<(B_ * C_ * H_ * W_ + 255) / 256, 256>>>(out);
}

// round 5
// speedup vs baseline: 4.9313x; 1.3540x over previous
#include <cuda_runtime.h>
#include <cuda_fp16.h>
#include <math.h>

// ---------------- constants ----------------
constexpr int B_   = 8;
constexpr int C_   = 2;
constexpr int H_   = 256;
constexpr int W_   = 64;
constexpr int PH_  = 4;
constexpr int PW_  = 4;
constexpr int HP_  = H_ / PH_;   // 64
constexpr int WP_  = W_ / PW_;   // 16
constexpr int N_   = HP_ * WP_;  // 1024
constexpr int HID_ = 1024;
constexpr int NH_  = 16;
constexpr int HD_  = HID_ / NH_; // 64
constexpr int DEPTH_ = 8;
constexpr int FFN_   = 2730;
constexpr int FFNP_  = 2752;     // padded to multiple of 64
constexpr int TDIM_  = 256;
constexpr int OUT_   = PH_ * PW_ * C_; // 32
constexpr int T_     = B_ * N_;        // 8192
constexpr float EPS_ = 1e-6f;

typedef unsigned short u16;
typedef unsigned int u32;

// ---------------- scratch (device globals; no allocs) ----------------
__device__ float g_h   [T_ * HID_];
__device__ u16   g_hn  [T_ * HID_];      // fp16 activations
__device__ float g_qkv [T_ * 3 * HID_];
__device__ float g_q   [T_ * HID_];      // [B*NH][N][HD]
__device__ float g_k   [T_ * HID_];      // [B*NH][N][HD]
__device__ float g_vT  [T_ * HID_];      // [B*NH][HD][N]
__device__ u16   g_ao  [T_ * HID_];      // fp16 [B][N][NH*HD]
__device__ float g_x12 [T_ * 2 * FFN_];
__device__ u16   g_ffn [T_ * FFNP_];     // fp16
__device__ float g_fin [T_ * OUT_];
__device__ float g_cs  [B_ * HID_];
__device__ float g_ada [DEPTH_ * B_ * 6 * HID_];
__device__ float g_fada[B_ * 2 * HID_];

// fp16 weights (pre-rounded)
__device__ u16 g_wq [DEPTH_ * 3 * HID_ * HID_];
__device__ u16 g_wp [DEPTH_ * HID_ * HID_];
__device__ u16 g_w12[DEPTH_ * 2 * FFN_ * HID_];
__device__ u16 g_w3 [DEPTH_ * HID_ * FFNP_];
__device__ u16 g_wf [OUT_ * HID_];

// ---------------- helpers ----------------
__device__ __forceinline__ void mmah(float* c, const unsigned* a, const unsigned* b) {
    asm volatile("mma.sync.aligned.m16n8k16.row.col.f32.f16.f16.f32 "
                 "{%0,%1,%2,%3},{%4,%5,%6,%7},{%8,%9},{%0,%1,%2,%3};"
                 : "+f"(c[0]), "+f"(c[1]), "+f"(c[2]), "+f"(c[3])
                 : "r"(a[0]), "r"(a[1]), "r"(a[2]), "r"(a[3]), "r"(b[0]), "r"(b[1]));
}
__device__ __forceinline__ void ldm4(unsigned* r, const u16* p) {
    unsigned addr = (unsigned)__cvta_generic_to_shared(p);
    asm volatile("ldmatrix.sync.aligned.m8n8.x4.shared.b16 {%0,%1,%2,%3}, [%4];"
                 : "=r"(r[0]), "=r"(r[1]), "=r"(r[2]), "=r"(r[3]) : "r"(addr));
}
__device__ __forceinline__ uint2 f4_to_h4(float4 v) {
    __half2 a = __floats2half2_rn(v.x, v.y);
    __half2 b = __floats2half2_rn(v.z, v.w);
    uint2 r; r.x = *reinterpret_cast<u32*>(&a); r.y = *reinterpret_cast<u32*>(&b);
    return r;
}
__device__ __forceinline__ void splith(float v, u16& h, u16& l) {
    __half hb = __float2half_rn(v);
    __half lb = __float2half_rn(v - __half2float(hb));
    h = *reinterpret_cast<u16*>(&hb);
    l = *reinterpret_cast<u16*>(&lb);
}
__device__ __forceinline__ u16 h16(float v) {
    __half hb = __float2half_rn(v);
    return *reinterpret_cast<u16*>(&hb);
}

// ---------------- fp16 GEMM: C = A @ W^T (+bias)(+gated residual) ----------------
// A: fp16 [M,K]; W: fp16 [Nout,K]. 128x128 tile, BK=16, double buffered.
constexpr int SROW_ = 24;

__global__ void __launch_bounds__(256)
k_gemm_h1(const u16* __restrict__ A, int lda,
          const u16* __restrict__ Wh, int ldw,
          float* __restrict__ C, int ldc,
          int M, int Nout, int K,
          const float* __restrict__ bias,
          const float* __restrict__ res,
          const float* __restrict__ gate, int gstride, int mode)
{
    __shared__ __align__(16) u16 sA[2][128 * SROW_];
    __shared__ __align__(16) u16 sB[2][128 * SROW_];

    int n0 = blockIdx.x * 128;
    int m0 = blockIdx.y * 128;
    int tid = threadIdx.x;
    int lane = tid & 31;
    int warp = tid >> 5;
    int wm = warp & 3;
    int wn = warp >> 2;

    int srow = tid >> 1;          // 0..127
    int scol = (tid & 1) * 8;     // 0 or 8

    const u16* Ap = A + (long long)(m0 + srow) * lda + scol;
    int wr = n0 + srow;
    const u16* Wp = Wh + (long long)wr * ldw + scol;
    bool wv = wr < Nout;

    int st = srow * SROW_ + scol;

    int aoff[2], boff[4];
#pragma unroll
    for (int mt = 0; mt < 2; mt++)
        aoff[mt] = (wm * 32 + mt * 16 + (lane & 15)) * SROW_ + ((lane >> 4) * 8);
#pragma unroll
    for (int q = 0; q < 4; q++)
        boff[q] = (wn * 64 + q * 16 + (lane & 7) + ((lane >> 4) << 3)) * SROW_
                + (((lane >> 3) & 1) * 8);

    float acc[2][8][4];
#pragma unroll
    for (int mt = 0; mt < 2; mt++)
#pragma unroll
        for (int nt = 0; nt < 8; nt++)
#pragma unroll
            for (int i = 0; i < 4; i++) acc[mt][nt][i] = 0.0f;

    const uint4 Z = make_uint4(0u, 0u, 0u, 0u);
    uint4 ra, rb;

    ra = *reinterpret_cast<const uint4*>(Ap);
    rb = wv ? *reinterpret_cast<const uint4*>(Wp) : Z;
    *reinterpret_cast<uint4*>(&sA[0][st]) = ra;
    *reinterpret_cast<uint4*>(&sB[0][st]) = rb;

    int ntiles = K / 16;
    int buf = 0;

    for (int t = 1; t <= ntiles; t++) {
        bool more = (t < ntiles);
        if (more) {
            int kt = t * 16;
            ra = *reinterpret_cast<const uint4*>(Ap + kt);
            rb = wv ? *reinterpret_cast<const uint4*>(Wp + kt) : Z;
        }
        __syncthreads();

        unsigned af[2][4];
        unsigned bf[8][2];
#pragma unroll
        for (int mt = 0; mt < 2; mt++)
            ldm4(af[mt], &sA[buf][aoff[mt]]);
#pragma unroll
        for (int q = 0; q < 4; q++) {
            unsigned r[4];
            ldm4(r, &sB[buf][boff[q]]);
            bf[2*q][0] = r[0]; bf[2*q][1] = r[1];
            bf[2*q+1][0] = r[2]; bf[2*q+1][1] = r[3];
        }
#pragma unroll
        for (int mt = 0; mt < 2; mt++)
#pragma unroll
            for (int nt = 0; nt < 8; nt++)
                mmah(acc[mt][nt], af[mt], bf[nt]);

        if (more) {
            int nb = buf ^ 1;
            *reinterpret_cast<uint4*>(&sA[nb][st]) = ra;
            *reinterpret_cast<uint4*>(&sB[nb][st]) = rb;
            buf = nb;
        }
    }

    // epilogue
#pragma unroll
    for (int mt = 0; mt < 2; mt++) {
        int row = m0 + wm * 32 + mt * 16 + (lane >> 2);
#pragma unroll
        for (int nt = 0; nt < 8; nt++) {
            int col = n0 + wn * 64 + nt * 8 + ((lane & 3) << 1);
#pragma unroll
            for (int i = 0; i < 4; i++) {
                int m = row + (i >> 1) * 8;
                int nn = col + (i & 1);
                if (nn < Nout) {
                    float v = acc[mt][nt][i];
                    if (bias) v += __ldg(bias + nn);
                    long long idx = (long long)m * ldc + nn;
                    if (mode == 1)
                        v = res[idx] + gate[(m >> 10) * gstride + nn] * v;
                    C[idx] = v;
                }
            }
        }
    }
}

// ---------------- weight conversion (fp32 -> fp16, with K padding) ----------------
__global__ void k_wcvt1(const float* __restrict__ src, u16* __restrict__ hi,
                        int srcK, int dstK, long long total)
{
    long long i = (long long)blockIdx.x * 256 + threadIdx.x;
    if (i >= total) return;
    int j = (int)(i % dstK);
    long long r = i / dstK;
    float v = (j < srcK) ? src[r * srcK + j] : 0.0f;
    hi[i] = h16(v);
}

// ---------------- fused flash attention ----------------
// grid (8 qblocks, B*NH). 256 threads. Q split fp16 2-term, K/V rounded fp16.
constexpr int FST = 72;  // u16 row stride
constexpr int FS_QH = 0;
constexpr int FS_QL = FS_QH + 128 * FST;
constexpr int FS_KH = FS_QL + 128 * FST;
constexpr int FS_VH = FS_KH + 64 * FST;
constexpr int FS_PH = FS_VH + 64 * FST;
constexpr int FS_PL = FS_PH + 128 * FST;
constexpr int FS_U16 = FS_PL + 128 * FST;            // in u16 units
constexpr int FS_SS = 0;                              // float offset after u16 area
constexpr int FS_SC = FS_SS + 128 * 66;
constexpr int FLASH_SMEM = FS_U16 * 2 + (FS_SC + 128) * 4;

__global__ void __launch_bounds__(256)
k_flash(const float* __restrict__ gq, const float* __restrict__ gk,
        const float* __restrict__ gvT, u16* __restrict__ gao)
{
    extern __shared__ __align__(16) char fsm[];
    u16* su = reinterpret_cast<u16*>(fsm);
    float* sf = reinterpret_cast<float*>(fsm + FS_U16 * 2);
    u16* sQh = su + FS_QH;
    u16* sQl = su + FS_QL;
    u16* sKh = su + FS_KH;
    u16* sVh = su + FS_VH;
    u16* sPh = su + FS_PH;
    u16* sPl = su + FS_PL;
    float* sS = sf + FS_SS;
    float* sSc = sf + FS_SC;

    int tid = threadIdx.x;
    int lane = tid & 31;
    int warp = tid >> 5;
    int wm = warp & 3;
    int wn = warp >> 2;

    int bh = blockIdx.y;
    int q0 = blockIdx.x * 128;
    const float* Qg = gq + ((long long)bh * N_ + q0) * HD_;
    const float* Kg = gk + (long long)bh * N_ * HD_;
    const float* Vg = gvT + (long long)bh * HD_ * N_;

    // load Q (x 0.125), split fp16 hi/lo
    {
        int r = tid >> 1, c0 = (tid & 1) * 32;
#pragma unroll
        for (int i = 0; i < 8; i++) {
            float4 v = *reinterpret_cast<const float4*>(Qg + (long long)r * HD_ + c0 + i * 4);
            v.x *= 0.125f; v.y *= 0.125f; v.z *= 0.125f; v.w *= 0.125f;
            u16 h[4], l[4];
            splith(v.x, h[0], l[0]); splith(v.y, h[1], l[1]);
            splith(v.z, h[2], l[2]); splith(v.w, h[3], l[3]);
            *reinterpret_cast<uint2*>(&sQh[r * FST + c0 + i * 4]) = *reinterpret_cast<uint2*>(h);
            *reinterpret_cast<uint2*>(&sQl[r * FST + c0 + i * 4]) = *reinterpret_cast<uint2*>(l);
        }
    }
    // load K,V chunk 0
    {
        int r = tid >> 2, fc = tid & 3;
#pragma unroll
        for (int i = 0; i < 4; i++) {
            int c = (fc * 4 + i) * 4;
            float4 kv = *reinterpret_cast<const float4*>(Kg + (long long)r * HD_ + c);
            float4 vv = *reinterpret_cast<const float4*>(Vg + (long long)r * N_ + c);
            *reinterpret_cast<uint2*>(&sKh[r * FST + c]) = f4_to_h4(kv);
            *reinterpret_cast<uint2*>(&sVh[r * FST + c]) = f4_to_h4(vv);
        }
    }
    __syncthreads();

    float m_st = -1e30f, l_st = 0.0f;
    float o[2][4][4];
#pragma unroll
    for (int mt = 0; mt < 2; mt++)
#pragma unroll
        for (int nt = 0; nt < 4; nt++)
#pragma unroll
            for (int i = 0; i < 4; i++) o[mt][nt][i] = 0.0f;

    int aoffA[2], boffB[2];
#pragma unroll
    for (int mt = 0; mt < 2; mt++)
        aoffA[mt] = (wm * 32 + mt * 16 + (lane & 15)) * FST + ((lane >> 4) * 8);
#pragma unroll
    for (int g = 0; g < 2; g++)
        boffB[g] = (wn * 32 + g * 16 + (lane & 7) + ((lane >> 4) << 3)) * FST
                 + (((lane >> 3) & 1) * 8);

    for (int c = 0; c < 16; c++) {
        // prefetch next K/V chunk
        float4 pk[4], pv[4];
        if (c < 15) {
            int r = tid >> 2, fc = tid & 3;
            long long kbase = (long long)(c + 1) * 64;
#pragma unroll
            for (int i = 0; i < 4; i++) {
                int cc = (fc * 4 + i) * 4;
                pk[i] = *reinterpret_cast<const float4*>(Kg + (kbase + r) * HD_ + cc);
                pv[i] = *reinterpret_cast<const float4*>(Vg + (long long)r * N_ + kbase + cc);
            }
        }

        // MMA1: S = (Qh + Ql) @ K^T
        float s[2][4][4];
#pragma unroll
        for (int mt = 0; mt < 2; mt++)
#pragma unroll
            for (int nt = 0; nt < 4; nt++)
#pragma unroll
                for (int i = 0; i < 4; i++) s[mt][nt][i] = 0.0f;
#pragma unroll
        for (int ks = 0; ks < 4; ks++) {
            unsigned ah[2][4], al[2][4], bk[4][2];
#pragma unroll
            for (int mt = 0; mt < 2; mt++) {
                ldm4(ah[mt], &sQh[aoffA[mt] + ks * 16]);
                ldm4(al[mt], &sQl[aoffA[mt] + ks * 16]);
            }
#pragma unroll
            for (int g = 0; g < 2; g++) {
                unsigned r[4];
                ldm4(r, &sKh[boffB[g] + ks * 16]);
                bk[2*g][0] = r[0]; bk[2*g][1] = r[1];
                bk[2*g+1][0] = r[2]; bk[2*g+1][1] = r[3];
            }
#pragma unroll
            for (int mt = 0; mt < 2; mt++)
#pragma unroll
                for (int nt = 0; nt < 4; nt++) {
                    mmah(s[mt][nt], ah[mt], bk[nt]);
                    mmah(s[mt][nt], al[mt], bk[nt]);
                }
        }
        // write S to smem
#pragma unroll
        for (int mt = 0; mt < 2; mt++) {
            int r0 = wm * 32 + mt * 16 + (lane >> 2);
#pragma unroll
            for (int nt = 0; nt < 4; nt++) {
                int col = wn * 32 + nt * 8 + (lane & 3) * 2;
                *reinterpret_cast<float2*>(&sS[r0 * 66 + col]) = make_float2(s[mt][nt][0], s[mt][nt][1]);
                *reinterpret_cast<float2*>(&sS[(r0 + 8) * 66 + col]) = make_float2(s[mt][nt][2], s[mt][nt][3]);
            }
        }
        __syncthreads();

        // online softmax (rows owned by tid<128)
        if (tid < 128) {
            const float* row = sS + tid * 66;
            float mx = m_st;
#pragma unroll
            for (int j = 0; j < 64; j++) mx = fmaxf(mx, row[j]);
            float corr = __expf(m_st - mx);
            float sum = 0.0f;
#pragma unroll
            for (int j0 = 0; j0 < 64; j0 += 4) {
                float p0 = __expf(row[j0+0] - mx);
                float p1 = __expf(row[j0+1] - mx);
                float p2 = __expf(row[j0+2] - mx);
                float p3 = __expf(row[j0+3] - mx);
                sum += (p0 + p1) + (p2 + p3);
                u16 h[4], l[4];
                splith(p0, h[0], l[0]); splith(p1, h[1], l[1]);
                splith(p2, h[2], l[2]); splith(p3, h[3], l[3]);
                *reinterpret_cast<uint2*>(&sPh[tid * FST + j0]) = *reinterpret_cast<uint2*>(h);
                *reinterpret_cast<uint2*>(&sPl[tid * FST + j0]) = *reinterpret_cast<uint2*>(l);
            }
            l_st = l_st * corr + sum;
            m_st = mx;
            sSc[tid] = corr;
        }
        __syncthreads();

        // rescale O and MMA2: O += (Ph + Pl) @ V^T
#pragma unroll
        for (int mt = 0; mt < 2; mt++) {
            int r0 = wm * 32 + mt * 16 + (lane >> 2);
            float f0 = sSc[r0], f1 = sSc[r0 + 8];
#pragma unroll
            for (int nt = 0; nt < 4; nt++) {
                o[mt][nt][0] *= f0; o[mt][nt][1] *= f0;
                o[mt][nt][2] *= f1; o[mt][nt][3] *= f1;
            }
        }
#pragma unroll
        for (int ks = 0; ks < 4; ks++) {
            unsigned ah[2][4], al[2][4], bv[4][2];
#pragma unroll
            for (int mt = 0; mt < 2; mt++) {
                ldm4(ah[mt], &sPh[aoffA[mt] + ks * 16]);
                ldm4(al[mt], &sPl[aoffA[mt] + ks * 16]);
            }
#pragma unroll
            for (int g = 0; g < 2; g++) {
                unsigned r[4];
                ldm4(r, &sVh[boffB[g] + ks * 16]);
                bv[2*g][0] = r[0]; bv[2*g][1] = r[1];
                bv[2*g+1][0] = r[2]; bv[2*g+1][1] = r[3];
            }
#pragma unroll
            for (int mt = 0; mt < 2; mt++)
#pragma unroll
                for (int nt = 0; nt < 4; nt++) {
                    mmah(o[mt][nt], ah[mt], bv[nt]);
                    mmah(o[mt][nt], al[mt], bv[nt]);
                }
        }
        __syncthreads();

        // commit prefetched K/V
        if (c < 15) {
            int r = tid >> 2, fc = tid & 3;
#pragma unroll
            for (int i = 0; i < 4; i++) {
                int cc = (fc * 4 + i) * 4;
                *reinterpret_cast<uint2*>(&sKh[r * FST + cc]) = f4_to_h4(pk[i]);
                *reinterpret_cast<uint2*>(&sVh[r * FST + cc]) = f4_to_h4(pv[i]);
            }
        }
        __syncthreads();
    }

    // final 1/l
    if (tid < 128) sSc[tid] = 1.0f / l_st;
    __syncthreads();

    int bb = bh >> 4, hh = bh & 15;
#pragma unroll
    for (int mt = 0; mt < 2; mt++) {
        int lr = wm * 32 + mt * 16 + (lane >> 2);
        float f0 = sSc[lr], f1 = sSc[lr + 8];
        int r0 = q0 + lr;
#pragma unroll
        for (int nt = 0; nt < 4; nt++) {
            int col = wn * 32 + nt * 8 + (lane & 3) * 2;
            long long a0 = ((long long)(bb * N_ + r0) * NH_ + hh) * HD_ + col;
            long long a1 = ((long long)(bb * N_ + r0 + 8) * NH_ + hh) * HD_ + col;
            __half2 v0 = __floats2half2_rn(o[mt][nt][0] * f0, o[mt][nt][1] * f0);
            __half2 v1 = __floats2half2_rn(o[mt][nt][2] * f1, o[mt][nt][3] * f1);
            *reinterpret_cast<u32*>(gao + a0) = *reinterpret_cast<u32*>(&v0);
            *reinterpret_cast<u32*>(gao + a1) = *reinterpret_cast<u32*>(&v1);
        }
    }
}

// ---------------- timestep embedding -> c -> silu(c) ----------------
__global__ void k_timestep(const float* __restrict__ t,
                           const float* __restrict__ t_w,
                           const float* __restrict__ t_b)
{
    int b = blockIdx.x;
    int tid = threadIdx.x;
    __shared__ float te[TDIM_];
    float tv = t[b];
    {
        int j = tid & 127;
        float f = __expf(-logf(10000.0f) * (float)j / 128.0f);
        float a = tv * f;
        te[tid] = (tid < 128) ? cosf(a) : sinf(a);
    }
    __syncthreads();
#pragma unroll
    for (int rep = 0; rep < 4; rep++) {
        int o = tid + rep * 256;
        float acc = t_b[o];
        const float* w = t_w + (long long)o * TDIM_;
        for (int j = 0; j < TDIM_; j += 4) {
            float4 wv = *reinterpret_cast<const float4*>(w + j);
            acc += te[j] * wv.x + te[j+1] * wv.y + te[j+2] * wv.z + te[j+3] * wv.w;
        }
        float sig = 1.0f / (1.0f + __expf(-acc));
        g_cs[b * HID_ + o] = acc * sig;
    }
}

// ---------------- all adaLN projections ----------------
__global__ void k_ada(const float* __restrict__ ada_w,
                      const float* __restrict__ ada_b,
                      const float* __restrict__ fada_w,
                      const float* __restrict__ fada_b)
{
    int d = blockIdx.x;
    int chunk = blockIdx.y;
    int tid = threadIdx.x;
    __shared__ float css[B_][HID_];
    for (int i = tid; i < B_ * HID_; i += 256)
        css[i >> 10][i & 1023] = g_cs[i];
    __syncthreads();

    int cnt = (d < DEPTH_) ? 6 * HID_ : 2 * HID_;
    int o = chunk * 256 + tid;
    if (o >= cnt) return;

    const float* W = (d < DEPTH_) ? ada_w + ((long long)d * 6 * HID_ + o) * HID_
                                  : fada_w + (long long)o * HID_;
    float bia = (d < DEPTH_) ? ada_b[d * 6 * HID_ + o] : fada_b[o];
    float acc[B_];
#pragma unroll
    for (int b = 0; b < B_; b++) acc[b] = bia;

    for (int j = 0; j < HID_; j += 4) {
        float4 wv = *reinterpret_cast<const float4*>(W + j);
#pragma unroll
        for (int b = 0; b < B_; b++) {
            acc[b] += css[b][j] * wv.x + css[b][j+1] * wv.y
                    + css[b][j+2] * wv.z + css[b][j+3] * wv.w;
        }
    }
#pragma unroll
    for (int b = 0; b < B_; b++) {
        if (d < DEPTH_) g_ada[((long long)(d * B_ + b)) * 6 * HID_ + o] = acc[b];
        else            g_fada[b * 2 * HID_ + o] = acc[b];
    }
}

// ---------------- patchify + bias + pos embed ----------------
__global__ void k_patch(const float* __restrict__ x,
                        const float* __restrict__ patch_w,
                        const float* __restrict__ patch_b)
{
    int tok = blockIdx.x;
    int b = tok >> 10;
    int n = tok & 1023;
    int hp = n >> 4;
    int wp = n & 15;
    int tid = threadIdx.x;
    __shared__ float xs[32];
    if (tid < 32) {
        int c = tid >> 4;
        int r = (tid >> 2) & 3;
        int q = tid & 3;
        xs[c * 16 + r * 4 + q] = x[((long long)(b * C_ + c) * H_ + hp * 4 + r) * W_ + wp * 4 + q];
    }
    __syncthreads();
    const float LOG1E4 = logf(10000.0f);
#pragma unroll
    for (int rep = 0; rep < 4; rep++) {
        int o = tid + rep * 256;
        float acc = patch_b[o];
        const float4* w4 = reinterpret_cast<const float4*>(patch_w + o * 32);
#pragma unroll
        for (int i = 0; i < 8; i++) {
            float4 wv = w4[i];
            acc += xs[i*4+0] * wv.x + xs[i*4+1] * wv.y + xs[i*4+2] * wv.z + xs[i*4+3] * wv.w;
        }
        int j = o & 255;
        int sec = o >> 8;
        float omega = __expf(-LOG1E4 * (float)j / 256.0f);
        float p = (sec < 2) ? (float)wp : (float)hp;
        float a = p * omega;
        float pos = (sec & 1) ? cosf(a) : sinf(a);
        g_h[(long long)tok * HID_ + o] = acc + pos;
    }
}

// ---------------- RMSNorm + modulate -> fp16 ----------------
__global__ void k_rmsmod(const float* __restrict__ in, u16* __restrict__ out,
                         const float* __restrict__ nw,
                         const float* __restrict__ ada, int ada_stride,
                         int shift_off, int scale_off)
{
    int tok = blockIdx.x;
    int b = tok >> 10;
    int tid = threadIdx.x;
    const float* row = in + (long long)tok * HID_;
    float v[4];
    float s = 0.0f;
#pragma unroll
    for (int i = 0; i < 4; i++) { v[i] = row[tid + i * 256]; s += v[i] * v[i]; }
    __shared__ float red[256];
    red[tid] = s; __syncthreads();
    for (int o = 128; o > 0; o >>= 1) { if (tid < o) red[tid] += red[tid + o]; __syncthreads(); }
    float rs = rsqrtf(red[0] / (float)HID_ + EPS_);
    const float* ar = ada + (long long)b * ada_stride;
    u16* orow = out + (long long)tok * HID_;
#pragma unroll
    for (int i = 0; i < 4; i++) {
        int cidx = tid + i * 256;
        orow[cidx] = h16(v[i] * rs * nw[cidx] * (1.0f + ar[scale_off + cidx]) + ar[shift_off + cidx]);
    }
}

// ---------------- per-head qk RMSNorm + RoPE + v transpose ----------------
__global__ void k_rope(const float* __restrict__ qn, const float* __restrict__ kn)
{
    int tok = blockIdx.x;
    int b = tok >> 10;
    int n = tok & 1023;
    int tid = threadIdx.x;
    int h = tid >> 4;
    int l = tid & 15;
    int d0 = l * 4;
    const float* row = g_qkv + (long long)tok * 3 * HID_;
    float4 q = *reinterpret_cast<const float4*>(row + h * HD_ + d0);
    float4 k = *reinterpret_cast<const float4*>(row + HID_ + h * HD_ + d0);
    float4 v = *reinterpret_cast<const float4*>(row + 2 * HID_ + h * HD_ + d0);

    float sq = q.x*q.x + q.y*q.y + q.z*q.z + q.w*q.w;
    float sk = k.x*k.x + k.y*k.y + k.z*k.z + k.w*k.w;
#pragma unroll
    for (int o = 1; o < 16; o <<= 1) {
        sq += __shfl_xor_sync(0xffffffffu, sq, o);
        sk += __shfl_xor_sync(0xffffffffu, sk, o);
    }
    float rq = rsqrtf(sq / (float)HD_ + EPS_);
    float rk = rsqrtf(sk / (float)HD_ + EPS_);
    q.x *= rq * qn[d0+0]; q.y *= rq * qn[d0+1]; q.z *= rq * qn[d0+2]; q.w *= rq * qn[d0+3];
    k.x *= rk * kn[d0+0]; k.y *= rk * kn[d0+1]; k.z *= rk * kn[d0+2]; k.w *= rk * kn[d0+3];

    const float LOG1E4 = logf(10000.0f);
    float hpos = (float)(n >> 4);
    float wpos = (float)(n & 15);
#pragma unroll
    for (int pr = 0; pr < 2; pr++) {
        int dp = d0 + pr * 2;
        int jj; float pos;
        if (dp < 32) { jj = dp;      pos = hpos; }
        else         { jj = dp - 32; pos = wpos; }
        float freq = __expf(-LOG1E4 * (float)jj / 32.0f);
        float ang = pos * freq;
        float c = cosf(ang), s = sinf(ang);
        float qx0 = (pr == 0) ? q.x : q.z;
        float qx1 = (pr == 0) ? q.y : q.w;
        float kx0 = (pr == 0) ? k.x : k.z;
        float kx1 = (pr == 0) ? k.y : k.w;
        float qy0 = qx0 * c - qx1 * s;
        float qy1 = qx1 * c + qx0 * s;
        float ky0 = kx0 * c - kx1 * s;
        float ky1 = kx1 * c + kx0 * s;
        if (pr == 0) { q.x = qy0; q.y = qy1; k.x = ky0; k.y = ky1; }
        else         { q.z = qy0; q.w = qy1; k.z = ky0; k.w = ky1; }
    }

    long long qbase = ((long long)(b * NH_ + h) * N_ + n) * HD_ + d0;
    *reinterpret_cast<float4*>(g_q + qbase) = q;
    *reinterpret_cast<float4*>(g_k + qbase) = k;
    long long vb = (long long)(b * NH_ + h) * HD_;
    g_vT[(vb + d0 + 0) * N_ + n] = v.x;
    g_vT[(vb + d0 + 1) * N_ + n] = v.y;
    g_vT[(vb + d0 + 2) * N_ + n] = v.z;
    g_vT[(vb + d0 + 3) * N_ + n] = v.w;
}

// ---------------- SwiGLU -> fp16 (padded) ----------------
__global__ void k_swiglu(u16* __restrict__ outp)
{
    long long idx = (long long)blockIdx.x * 256 + threadIdx.x;
    if (idx >= (long long)T_ * FFNP_) return;
    int j = (int)(idx % FFNP_);
    long long m = idx / FFNP_;
    float out = 0.0f;
    if (j < FFN_) {
        float a = g_x12[m * (2 * FFN_) + j];
        float b = g_x12[m * (2 * FFN_) + FFN_ + j];
        out = a / (1.0f + __expf(-a)) * b;
    }
    outp[idx] = h16(out);
}

// ---------------- unpatchify ----------------
__global__ void k_unpatch(float* __restrict__ out)
{
    int idx = blockIdx.x * 256 + threadIdx.x;
    if (idx >= B_ * C_ * H_ * W_) return;
    int ww = idx % W_;
    int tmp = idx / W_;
    int hh = tmp % H_;
    int tmp2 = tmp / H_;
    int c = tmp2 % C_;
    int b = tmp2 / C_;
    int hp = hh >> 2, p = hh & 3;
    int wp = ww >> 2, q = ww & 3;
    out[idx] = g_fin[((long long)(b * N_ + hp * WP_ + wp)) * OUT_ + p * (PW_ * C_) + q * C_ + c];
}

// ---------------- host orchestration ----------------
extern "C" void kernel_launch(void* const* d_in, const int* in_sizes, int n_in,
                              void* d_out, int out_size)
{
    const float* x       = (const float*)d_in[0];
    const float* t       = (const float*)d_in[1];
    const float* patch_w = (const float*)d_in[2];
    const float* patch_b = (const float*)d_in[3];
    const float* t_w     = (const float*)d_in[4];
    const float* t_b     = (const float*)d_in[5];
    const float* norm1_w = (const float*)d_in[6];
    const float* qkv_w   = (const float*)d_in[7];
    const float* qkv_b   = (const float*)d_in[8];
    const float* qn_w    = (const float*)d_in[9];
    const float* kn_w    = (const float*)d_in[10];
    const float* proj_w  = (const float*)d_in[11];
    const float* proj_b  = (const float*)d_in[12];
    const float* norm2_w = (const float*)d_in[13];
    const float* w12_w   = (const float*)d_in[14];
    const float* w12_b   = (const float*)d_in[15];
    const float* w3_w    = (const float*)d_in[16];
    const float* w3_b    = (const float*)d_in[17];
    const float* ada_w   = (const float*)d_in[18];
    const float* ada_b   = (const float*)d_in[19];
    const float* fnorm_w = (const float*)d_in[20];
    const float* flin_w  = (const float*)d_in[21];
    const float* flin_b  = (const float*)d_in[22];
    const float* fada_w  = (const float*)d_in[23];
    const float* fada_b  = (const float*)d_in[24];
    float* out = (float*)d_out;

    cudaFuncSetAttribute(k_flash, cudaFuncAttributeMaxDynamicSharedMemorySize, FLASH_SMEM);

    float *p_h, *p_qkv, *p_q, *p_k, *p_vT, *p_x12, *p_fin, *p_ada, *p_fada;
    u16 *p_hn, *p_ao, *p_ffn, *p_wq, *p_wp, *p_w12, *p_w3, *p_wf;
    cudaGetSymbolAddress((void**)&p_h,   g_h);
    cudaGetSymbolAddress((void**)&p_hn,  g_hn);
    cudaGetSymbolAddress((void**)&p_qkv, g_qkv);
    cudaGetSymbolAddress((void**)&p_q,   g_q);
    cudaGetSymbolAddress((void**)&p_k,   g_k);
    cudaGetSymbolAddress((void**)&p_vT,  g_vT);
    cudaGetSymbolAddress((void**)&p_ao,  g_ao);
    cudaGetSymbolAddress((void**)&p_x12, g_x12);
    cudaGetSymbolAddress((void**)&p_ffn, g_ffn);
    cudaGetSymbolAddress((void**)&p_fin, g_fin);
    cudaGetSymbolAddress((void**)&p_ada, g_ada);
    cudaGetSymbolAddress((void**)&p_fada, g_fada);
    cudaGetSymbolAddress((void**)&p_wq,  g_wq);
    cudaGetSymbolAddress((void**)&p_wp,  g_wp);
    cudaGetSymbolAddress((void**)&p_w12, g_w12);
    cudaGetSymbolAddress((void**)&p_w3,  g_w3);
    cudaGetSymbolAddress((void**)&p_wf,  g_wf);

    auto cvt = [](const float* src, u16* hi, int srcK, int dstK, long long rows) {
        long long total = rows * dstK;
        k_wcvt1<<<(unsigned)((total + 255) / 256), 256>>>(src, hi, srcK, dstK, total);
    };

    auto gemm = [](const u16* A, int lda, const u16* Wh, int ldw,
                   float* C, int ldc, int M, int Nout, int K,
                   const float* bias, const float* res,
                   const float* gate, int gstride, int mode) {
        dim3 grid((Nout + 127) / 128, M / 128);
        k_gemm_h1<<<grid, 256>>>(A, lda, Wh, ldw, C, ldc, M, Nout, K,
                                 bias, res, gate, gstride, mode);
    };

    // setup
    k_timestep<<<B_, 256>>>(t, t_w, t_b);
    k_ada<<<dim3(DEPTH_ + 1, 24), 256>>>(ada_w, ada_b, fada_w, fada_b);
    cvt(qkv_w, p_wq, HID_, HID_, (long long)DEPTH_ * 3 * HID_);
    cvt(proj_w, p_wp, HID_, HID_, (long long)DEPTH_ * HID_);
    cvt(w12_w, p_w12, HID_, HID_, (long long)DEPTH_ * 2 * FFN_);
    cvt(w3_w, p_w3, FFN_, FFNP_, (long long)DEPTH_ * HID_);
    cvt(flin_w, p_wf, HID_, HID_, OUT_);
    k_patch<<<T_, 256>>>(x, patch_w, patch_b);

    for (int d = 0; d < DEPTH_; d++) {
        const float* adab = p_ada + (long long)d * B_ * 6 * HID_;

        // norm1 + modulate -> fp16
        k_rmsmod<<<T_, 256>>>(p_h, p_hn, norm1_w + d * HID_, adab, 6 * HID_, 0, HID_);

        // qkv
        gemm(p_hn, HID_, p_wq + (long long)d * 3 * HID_ * HID_, HID_,
             p_qkv, 3 * HID_, T_, 3 * HID_, HID_,
             qkv_b + d * 3 * HID_, nullptr, nullptr, 0, 0);

        // qk-norm + rope + v transpose
        k_rope<<<T_, 256>>>(qn_w + d * HD_, kn_w + d * HD_);

        // fused flash attention -> g_ao (fp16)
        k_flash<<<dim3(N_ / 128, B_ * NH_), 256, FLASH_SMEM>>>(p_q, p_k, p_vT, p_ao);

        // proj + gated residual (gm)
        gemm(p_ao, HID_, p_wp + (long long)d * HID_ * HID_, HID_,
             p_h, HID_, T_, HID_, HID_,
             proj_b + d * HID_, p_h, adab + 2 * HID_, 6 * HID_, 1);

        // norm2 + modulate -> fp16
        k_rmsmod<<<T_, 256>>>(p_h, p_hn, norm2_w + d * HID_, adab, 6 * HID_, 3 * HID_, 4 * HID_);

        // w12
        gemm(p_hn, HID_, p_w12 + (long long)d * 2 * FFN_ * HID_, HID_,
             p_x12, 2 * FFN_, T_, 2 * FFN_, HID_,
             w12_b + d * 2 * FFN_, nullptr, nullptr, 0, 0);

        // swiglu -> fp16 (padded)
        {
            long long tot = (long long)T_ * FFNP_;
            k_swiglu<<<(unsigned)((tot + 255) / 256), 256>>>(p_ffn);
        }

        // w3 + gated residual (gp)
        gemm(p_ffn, FFNP_, p_w3 + (long long)d * HID_ * FFNP_, FFNP_,
             p_h, HID_, T_, HID_, FFNP_,
             w3_b + d * HID_, p_h, adab + 5 * HID_, 6 * HID_, 1);
    }

    // final norm + modulate -> fp16
    k_rmsmod<<<T_, 256>>>(p_h, p_hn, fnorm_w, p_fada, 2 * HID_, 0, HID_);

    // final linear
    gemm(p_hn, HID_, p_wf, HID_,
         p_fin, OUT_, T_, OUT_, HID_,
         flin_b, nullptr, nullptr, 0, 0);

    k_unpatch<<<(B_ * C_ * H_ * W_ + 255) / 256, 256>>>(out);
}

// round 6
// speedup vs baseline: 5.8574x; 1.1878x over previous
#include <cuda_runtime.h>
#include <cuda_fp16.h>
#include <math.h>

// ---------------- constants ----------------
constexpr int B_   = 8;
constexpr int C_   = 2;
constexpr int H_   = 256;
constexpr int W_   = 64;
constexpr int PH_  = 4;
constexpr int PW_  = 4;
constexpr int HP_  = H_ / PH_;   // 64
constexpr int WP_  = W_ / PW_;   // 16
constexpr int N_   = HP_ * WP_;  // 1024
constexpr int HID_ = 1024;
constexpr int NH_  = 16;
constexpr int HD_  = HID_ / NH_; // 64
constexpr int DEPTH_ = 8;
constexpr int FFN_   = 2730;
constexpr int FFNP_  = 2752;     // padded to multiple of 64
constexpr int NW12_  = 2 * FFNP_; // 5504 interleaved rows
constexpr int TDIM_  = 256;
constexpr int OUT_   = PH_ * PW_ * C_; // 32
constexpr int OUTP_  = 128;            // padded final rows
constexpr int T_     = B_ * N_;        // 8192
constexpr float EPS_ = 1e-6f;

typedef unsigned short u16;
typedef unsigned int u32;

// ---------------- scratch (device globals; no allocs) ----------------
__device__ float g_h    [T_ * HID_];
__device__ u16   g_hn   [T_ * HID_];       // fp16 activations
__device__ u16   g_qkv  [T_ * 3 * HID_];   // fp16 qkv GEMM output
__device__ float g_q    [T_ * HID_];       // fp32 [B*NH][N][HD]
__device__ u16   g_k    [T_ * HID_];       // fp16 [B*NH][N][HD]
__device__ u16   g_vT   [T_ * HID_];       // fp16 [B*NH][HD][N]
__device__ u16   g_ao   [T_ * HID_];       // fp16 [B][N][NH*HD]
__device__ u16   g_ffn  [T_ * FFNP_];      // fp16 swiglu output
__device__ float g_fin  [T_ * OUT_];
__device__ float g_cs   [B_ * HID_];
__device__ float g_ada  [DEPTH_ * B_ * 6 * HID_];
__device__ float g_fada [B_ * 2 * HID_];

// fp16 weights (pre-rounded, padded)
__device__ u16 g_wq [DEPTH_ * 3 * HID_ * HID_];
__device__ u16 g_wp [DEPTH_ * HID_ * HID_];
__device__ u16 g_w12[DEPTH_ * NW12_ * HID_];     // interleaved: row 2j=w1_j, 2j+1=w2_j
__device__ u16 g_w3 [DEPTH_ * HID_ * FFNP_];
__device__ u16 g_wf [OUTP_ * HID_];

// ---------------- helpers ----------------
__device__ __forceinline__ void mmah(float* c, const unsigned* a, const unsigned* b) {
    asm volatile("mma.sync.aligned.m16n8k16.row.col.f32.f16.f16.f32 "
                 "{%0,%1,%2,%3},{%4,%5,%6,%7},{%8,%9},{%0,%1,%2,%3};"
                 : "+f"(c[0]), "+f"(c[1]), "+f"(c[2]), "+f"(c[3])
                 : "r"(a[0]), "r"(a[1]), "r"(a[2]), "r"(a[3]), "r"(b[0]), "r"(b[1]));
}
__device__ __forceinline__ void ldm4(unsigned* r, const u16* p) {
    unsigned addr = (unsigned)__cvta_generic_to_shared(p);
    asm volatile("ldmatrix.sync.aligned.m8n8.x4.shared.b16 {%0,%1,%2,%3}, [%4];"
                 : "=r"(r[0]), "=r"(r[1]), "=r"(r[2]), "=r"(r[3]) : "r"(addr));
}
__device__ __forceinline__ void cpa16(u32 dst, const void* src) {
    asm volatile("cp.async.ca.shared.global [%0], [%1], 16;" :: "r"(dst), "l"(src));
}
#define CP_COMMIT asm volatile("cp.async.commit_group;")
#define CP_WAIT2  asm volatile("cp.async.wait_group 2;")

__device__ __forceinline__ void splith(float v, u16& h, u16& l) {
    __half hb = __float2half_rn(v);
    __half lb = __float2half_rn(v - __half2float(hb));
    h = *reinterpret_cast<u16*>(&hb);
    l = *reinterpret_cast<u16*>(&lb);
}
__device__ __forceinline__ u16 h16(float v) {
    __half hb = __float2half_rn(v);
    return *reinterpret_cast<u16*>(&hb);
}
__device__ __forceinline__ float2 h2f(u32 p) {
    return __half22float2(*reinterpret_cast<__half2*>(&p));
}
__device__ __forceinline__ u32 f2h2(float a, float b) {
    __half2 t = __floats2half2_rn(a, b);
    return *reinterpret_cast<u32*>(&t);
}

// ---------------- fp16 pipelined GEMM ----------------
// C = A(fp16)[M,K] @ W(fp16)[Npad,K]^T, epilogue modes:
//  0: fp32 out (+bias)   1: fp32 gated residual   2: swiglu fp16 (interleaved w12)
//  3: fp16 out (+bias)
constexpr int SROW_ = 24;
constexpr int STG_  = 4;
constexpr int STGB_ = 128 * SROW_ * 2;   // bytes per stage

__global__ void __launch_bounds__(256, 2)
k_gemm_h1(const u16* __restrict__ A, int lda,
          const u16* __restrict__ W, int ldw,
          void* __restrict__ Cv, int ldc,
          int M, int Nout, int K,
          const float* __restrict__ bias,
          const float* __restrict__ res,
          const float* __restrict__ gate, int gstride, int mode)
{
    __shared__ __align__(16) u16 sA[STG_][128 * SROW_];
    __shared__ __align__(16) u16 sB[STG_][128 * SROW_];

    int n0 = blockIdx.x * 128;
    int m0 = blockIdx.y * 128;
    int tid = threadIdx.x;
    int lane = tid & 31;
    int warp = tid >> 5;
    int wm = warp & 3;
    int wn = warp >> 2;

    int srow = tid >> 1;          // 0..127
    int scol = (tid & 1) * 8;     // 0 or 8

    const u16* Ap = A + (long long)(m0 + srow) * lda + scol;
    const u16* Wp = W + (long long)(n0 + srow) * ldw + scol;

    u32 baseA = (u32)__cvta_generic_to_shared(&sA[0][0]) + (u32)(srow * SROW_ + scol) * 2;
    u32 baseB = (u32)__cvta_generic_to_shared(&sB[0][0]) + (u32)(srow * SROW_ + scol) * 2;

    int aoff[2], boff[4];
#pragma unroll
    for (int mt = 0; mt < 2; mt++)
        aoff[mt] = (wm * 32 + mt * 16 + (lane & 15)) * SROW_ + ((lane >> 4) * 8);
#pragma unroll
    for (int q = 0; q < 4; q++)
        boff[q] = (wn * 64 + q * 16 + (lane & 7) + ((lane >> 4) << 3)) * SROW_
                + (((lane >> 3) & 1) * 8);

    float acc[2][8][4];
#pragma unroll
    for (int mt = 0; mt < 2; mt++)
#pragma unroll
        for (int nt = 0; nt < 8; nt++)
#pragma unroll
            for (int i = 0; i < 4; i++) acc[mt][nt][i] = 0.0f;

    int ntiles = K / 16;

#define ISSUE(t) do { \
        u32 off_ = (u32)((t) & 3) * STGB_; \
        cpa16(baseA + off_, Ap + (t) * 16); \
        cpa16(baseB + off_, Wp + (t) * 16); \
        CP_COMMIT; \
    } while (0)

    ISSUE(0); ISSUE(1); ISSUE(2);

    for (int t = 0; t < ntiles; t++) {
        CP_WAIT2;
        __syncthreads();
        if (t + 3 < ntiles) ISSUE(t + 3);
        int buf = t & 3;

        unsigned af[2][4];
        unsigned bf[8][2];
#pragma unroll
        for (int mt = 0; mt < 2; mt++)
            ldm4(af[mt], &sA[buf][aoff[mt]]);
#pragma unroll
        for (int q = 0; q < 4; q++) {
            unsigned r[4];
            ldm4(r, &sB[buf][boff[q]]);
            bf[2*q][0] = r[0]; bf[2*q][1] = r[1];
            bf[2*q+1][0] = r[2]; bf[2*q+1][1] = r[3];
        }
#pragma unroll
        for (int mt = 0; mt < 2; mt++)
#pragma unroll
            for (int nt = 0; nt < 8; nt++)
                mmah(acc[mt][nt], af[mt], bf[nt]);
    }
#undef ISSUE

    // ---- epilogue ----
#pragma unroll
    for (int mt = 0; mt < 2; mt++) {
        int row = m0 + wm * 32 + mt * 16 + (lane >> 2);
#pragma unroll
        for (int nt = 0; nt < 8; nt++) {
            int col = n0 + wn * 64 + nt * 8 + ((lane & 3) << 1);
#pragma unroll
            for (int half = 0; half < 2; half++) {
                int m = row + half * 8;
                float a0 = acc[mt][nt][half * 2 + 0];
                float a1 = acc[mt][nt][half * 2 + 1];
                if (mode == 2) {
                    // interleaved swiglu: col even = x1_j, odd = x2_j, j = col>>1
                    int j = col >> 1;
                    float b1 = 0.0f, b2 = 0.0f;
                    if (j < FFN_) { b1 = __ldg(bias + j); b2 = __ldg(bias + FFN_ + j); }
                    float x1 = a0 + b1, x2 = a1 + b2;
                    float r = x1 / (1.0f + __expf(-x1)) * x2;
                    ((u16*)Cv)[(long long)m * FFNP_ + j] = h16(r);
                } else if (mode == 3) {
                    if (col < Nout) {
                        float v0 = a0 + __ldg(bias + col);
                        float v1 = a1 + __ldg(bias + col + 1);
                        *reinterpret_cast<u32*>((u16*)Cv + (long long)m * ldc + col) = f2h2(v0, v1);
                    }
                } else {
                    float* C = (float*)Cv;
#pragma unroll
                    for (int e = 0; e < 2; e++) {
                        int nn = col + e;
                        if (nn < Nout) {
                            float v = (e == 0) ? a0 : a1;
                            if (bias) v += __ldg(bias + nn);
                            long long idx = (long long)m * ldc + nn;
                            if (mode == 1)
                                v = res[idx] + gate[(m >> 10) * gstride + nn] * v;
                            C[idx] = v;
                        }
                    }
                }
            }
        }
    }
}

// ---------------- weight conversion (fp32 -> fp16, row/K padding) ----------------
__global__ void k_wcvt(const float* __restrict__ src, u16* __restrict__ dst,
                       int srcK, int dstK, int srcRows, int dstRows, long long total)
{
    long long i = (long long)blockIdx.x * 256 + threadIdx.x;
    if (i >= total) return;
    int j = (int)(i % dstK);
    long long r = i / dstK;
    long long mat = r / dstRows;
    int rr = (int)(r % dstRows);
    float v = 0.0f;
    if (rr < srcRows && j < srcK)
        v = src[(mat * srcRows + rr) * (long long)srcK + j];
    dst[i] = h16(v);
}

// w12 interleave: dst row r2 in [0,NW12): pair j=r2>>1, half=r2&1 -> src row half*FFN+j
__global__ void k_wcvt12(const float* __restrict__ src, u16* __restrict__ dst)
{
    long long i = (long long)blockIdx.x * 256 + threadIdx.x;
    if (i >= (long long)DEPTH_ * NW12_ * HID_) return;
    int j = (int)(i % HID_);
    long long r = i / HID_;
    int d = (int)(r / NW12_);
    int r2 = (int)(r % NW12_);
    int pj = r2 >> 1;
    int hf = r2 & 1;
    float v = 0.0f;
    if (pj < FFN_)
        v = src[((long long)d * 2 * FFN_ + hf * FFN_ + pj) * HID_ + j];
    dst[i] = h16(v);
}

// ---------------- fused flash attention ----------------
constexpr int FST = 72;  // u16 row stride
constexpr int FS_QH = 0;
constexpr int FS_QL = FS_QH + 128 * FST;
constexpr int FS_KH = FS_QL + 128 * FST;
constexpr int FS_VH = FS_KH + 64 * FST;
constexpr int FS_PH = FS_VH + 64 * FST;
constexpr int FS_PL = FS_PH + 128 * FST;
constexpr int FS_U16 = FS_PL + 128 * FST;
constexpr int FS_SS = 0;
constexpr int FS_SC = FS_SS + 128 * 66;
constexpr int FLASH_SMEM = FS_U16 * 2 + (FS_SC + 128) * 4;

__global__ void __launch_bounds__(256)
k_flash(const float* __restrict__ gq, const u16* __restrict__ gk,
        const u16* __restrict__ gvT, u16* __restrict__ gao)
{
    extern __shared__ __align__(16) char fsm[];
    u16* su = reinterpret_cast<u16*>(fsm);
    float* sf = reinterpret_cast<float*>(fsm + FS_U16 * 2);
    u16* sQh = su + FS_QH;
    u16* sQl = su + FS_QL;
    u16* sKh = su + FS_KH;
    u16* sVh = su + FS_VH;
    u16* sPh = su + FS_PH;
    u16* sPl = su + FS_PL;
    float* sS = sf + FS_SS;
    float* sSc = sf + FS_SC;

    int tid = threadIdx.x;
    int lane = tid & 31;
    int warp = tid >> 5;
    int wm = warp & 3;
    int wn = warp >> 2;

    int bh = blockIdx.y;
    int q0 = blockIdx.x * 128;
    const float* Qg = gq + ((long long)bh * N_ + q0) * HD_;
    const u16* Kg = gk + (long long)bh * N_ * HD_;
    const u16* Vg = gvT + (long long)bh * HD_ * N_;

    // load Q (x 0.125), split fp16 hi/lo
    {
        int r = tid >> 1, c0 = (tid & 1) * 32;
#pragma unroll
        for (int i = 0; i < 8; i++) {
            float4 v = *reinterpret_cast<const float4*>(Qg + (long long)r * HD_ + c0 + i * 4);
            v.x *= 0.125f; v.y *= 0.125f; v.z *= 0.125f; v.w *= 0.125f;
            u16 h[4], l[4];
            splith(v.x, h[0], l[0]); splith(v.y, h[1], l[1]);
            splith(v.z, h[2], l[2]); splith(v.w, h[3], l[3]);
            *reinterpret_cast<uint2*>(&sQh[r * FST + c0 + i * 4]) = *reinterpret_cast<uint2*>(h);
            *reinterpret_cast<uint2*>(&sQl[r * FST + c0 + i * 4]) = *reinterpret_cast<uint2*>(l);
        }
    }
    // load K,V chunk 0 (fp16 direct copy)
    int kr = tid >> 2, kfc = (tid & 3) * 16;
    {
        const u16* ks = Kg + (long long)kr * HD_ + kfc;
        const u16* vs = Vg + (long long)kr * N_ + kfc;
        *reinterpret_cast<uint4*>(&sKh[kr * FST + kfc]) = *reinterpret_cast<const uint4*>(ks);
        *reinterpret_cast<uint4*>(&sKh[kr * FST + kfc + 8]) = *reinterpret_cast<const uint4*>(ks + 8);
        *reinterpret_cast<uint4*>(&sVh[kr * FST + kfc]) = *reinterpret_cast<const uint4*>(vs);
        *reinterpret_cast<uint4*>(&sVh[kr * FST + kfc + 8]) = *reinterpret_cast<const uint4*>(vs + 8);
    }
    __syncthreads();

    float m_st = -1e30f, l_st = 0.0f;
    float o[2][4][4];
#pragma unroll
    for (int mt = 0; mt < 2; mt++)
#pragma unroll
        for (int nt = 0; nt < 4; nt++)
#pragma unroll
            for (int i = 0; i < 4; i++) o[mt][nt][i] = 0.0f;

    int aoffA[2], boffB[2];
#pragma unroll
    for (int mt = 0; mt < 2; mt++)
        aoffA[mt] = (wm * 32 + mt * 16 + (lane & 15)) * FST + ((lane >> 4) * 8);
#pragma unroll
    for (int g = 0; g < 2; g++)
        boffB[g] = (wn * 32 + g * 16 + (lane & 7) + ((lane >> 4) << 3)) * FST
                 + (((lane >> 3) & 1) * 8);

    for (int c = 0; c < 16; c++) {
        // prefetch next K/V chunk
        uint4 pk0, pk1, pv0, pv1;
        if (c < 15) {
            long long kbase = (long long)(c + 1) * 64;
            const u16* ks = Kg + (kbase + kr) * HD_ + kfc;
            const u16* vs = Vg + (long long)kr * N_ + kbase + kfc;
            pk0 = *reinterpret_cast<const uint4*>(ks);
            pk1 = *reinterpret_cast<const uint4*>(ks + 8);
            pv0 = *reinterpret_cast<const uint4*>(vs);
            pv1 = *reinterpret_cast<const uint4*>(vs + 8);
        }

        // MMA1: S = (Qh + Ql) @ K^T
        float s[2][4][4];
#pragma unroll
        for (int mt = 0; mt < 2; mt++)
#pragma unroll
            for (int nt = 0; nt < 4; nt++)
#pragma unroll
                for (int i = 0; i < 4; i++) s[mt][nt][i] = 0.0f;
#pragma unroll
        for (int ks = 0; ks < 4; ks++) {
            unsigned ah[2][4], al[2][4], bk[4][2];
#pragma unroll
            for (int mt = 0; mt < 2; mt++) {
                ldm4(ah[mt], &sQh[aoffA[mt] + ks * 16]);
                ldm4(al[mt], &sQl[aoffA[mt] + ks * 16]);
            }
#pragma unroll
            for (int g = 0; g < 2; g++) {
                unsigned r[4];
                ldm4(r, &sKh[boffB[g] + ks * 16]);
                bk[2*g][0] = r[0]; bk[2*g][1] = r[1];
                bk[2*g+1][0] = r[2]; bk[2*g+1][1] = r[3];
            }
#pragma unroll
            for (int mt = 0; mt < 2; mt++)
#pragma unroll
                for (int nt = 0; nt < 4; nt++) {
                    mmah(s[mt][nt], ah[mt], bk[nt]);
                    mmah(s[mt][nt], al[mt], bk[nt]);
                }
        }
        // write S to smem
#pragma unroll
        for (int mt = 0; mt < 2; mt++) {
            int r0 = wm * 32 + mt * 16 + (lane >> 2);
#pragma unroll
            for (int nt = 0; nt < 4; nt++) {
                int col = wn * 32 + nt * 8 + (lane & 3) * 2;
                *reinterpret_cast<float2*>(&sS[r0 * 66 + col]) = make_float2(s[mt][nt][0], s[mt][nt][1]);
                *reinterpret_cast<float2*>(&sS[(r0 + 8) * 66 + col]) = make_float2(s[mt][nt][2], s[mt][nt][3]);
            }
        }
        __syncthreads();

        // online softmax
        if (tid < 128) {
            const float* row = sS + tid * 66;
            float mx = m_st;
#pragma unroll
            for (int j = 0; j < 64; j++) mx = fmaxf(mx, row[j]);
            float corr = __expf(m_st - mx);
            float sum = 0.0f;
#pragma unroll
            for (int j0 = 0; j0 < 64; j0 += 4) {
                float p0 = __expf(row[j0+0] - mx);
                float p1 = __expf(row[j0+1] - mx);
                float p2 = __expf(row[j0+2] - mx);
                float p3 = __expf(row[j0+3] - mx);
                sum += (p0 + p1) + (p2 + p3);
                u16 h[4], l[4];
                splith(p0, h[0], l[0]); splith(p1, h[1], l[1]);
                splith(p2, h[2], l[2]); splith(p3, h[3], l[3]);
                *reinterpret_cast<uint2*>(&sPh[tid * FST + j0]) = *reinterpret_cast<uint2*>(h);
                *reinterpret_cast<uint2*>(&sPl[tid * FST + j0]) = *reinterpret_cast<uint2*>(l);
            }
            l_st = l_st * corr + sum;
            m_st = mx;
            sSc[tid] = corr;
        }
        __syncthreads();

        // rescale O and MMA2: O += (Ph + Pl) @ V^T
#pragma unroll
        for (int mt = 0; mt < 2; mt++) {
            int r0 = wm * 32 + mt * 16 + (lane >> 2);
            float f0 = sSc[r0], f1 = sSc[r0 + 8];
#pragma unroll
            for (int nt = 0; nt < 4; nt++) {
                o[mt][nt][0] *= f0; o[mt][nt][1] *= f0;
                o[mt][nt][2] *= f1; o[mt][nt][3] *= f1;
            }
        }
#pragma unroll
        for (int ks = 0; ks < 4; ks++) {
            unsigned ah[2][4], al[2][4], bv[4][2];
#pragma unroll
            for (int mt = 0; mt < 2; mt++) {
                ldm4(ah[mt], &sPh[aoffA[mt] + ks * 16]);
                ldm4(al[mt], &sPl[aoffA[mt] + ks * 16]);
            }
#pragma unroll
            for (int g = 0; g < 2; g++) {
                unsigned r[4];
                ldm4(r, &sVh[boffB[g] + ks * 16]);
                bv[2*g][0] = r[0]; bv[2*g][1] = r[1];
                bv[2*g+1][0] = r[2]; bv[2*g+1][1] = r[3];
            }
#pragma unroll
            for (int mt = 0; mt < 2; mt++)
#pragma unroll
                for (int nt = 0; nt < 4; nt++) {
                    mmah(o[mt][nt], ah[mt], bv[nt]);
                    mmah(o[mt][nt], al[mt], bv[nt]);
                }
        }
        __syncthreads();

        // commit prefetched K/V
        if (c < 15) {
            *reinterpret_cast<uint4*>(&sKh[kr * FST + kfc]) = pk0;
            *reinterpret_cast<uint4*>(&sKh[kr * FST + kfc + 8]) = pk1;
            *reinterpret_cast<uint4*>(&sVh[kr * FST + kfc]) = pv0;
            *reinterpret_cast<uint4*>(&sVh[kr * FST + kfc + 8]) = pv1;
        }
        __syncthreads();
    }

    // final 1/l
    if (tid < 128) sSc[tid] = 1.0f / l_st;
    __syncthreads();

    int bb = bh >> 4, hh = bh & 15;
#pragma unroll
    for (int mt = 0; mt < 2; mt++) {
        int lr = wm * 32 + mt * 16 + (lane >> 2);
        float f0 = sSc[lr], f1 = sSc[lr + 8];
        int r0 = q0 + lr;
#pragma unroll
        for (int nt = 0; nt < 4; nt++) {
            int col = wn * 32 + nt * 8 + (lane & 3) * 2;
            long long a0 = ((long long)(bb * N_ + r0) * NH_ + hh) * HD_ + col;
            long long a1 = ((long long)(bb * N_ + r0 + 8) * NH_ + hh) * HD_ + col;
            *reinterpret_cast<u32*>(gao + a0) = f2h2(o[mt][nt][0] * f0, o[mt][nt][1] * f0);
            *reinterpret_cast<u32*>(gao + a1) = f2h2(o[mt][nt][2] * f1, o[mt][nt][3] * f1);
        }
    }
}

// ---------------- timestep embedding -> c -> silu(c) ----------------
__global__ void k_timestep(const float* __restrict__ t,
                           const float* __restrict__ t_w,
                           const float* __restrict__ t_b)
{
    int b = blockIdx.x;
    int tid = threadIdx.x;
    __shared__ float te[TDIM_];
    float tv = t[b];
    {
        int j = tid & 127;
        float f = __expf(-logf(10000.0f) * (float)j / 128.0f);
        float a = tv * f;
        te[tid] = (tid < 128) ? cosf(a) : sinf(a);
    }
    __syncthreads();
#pragma unroll
    for (int rep = 0; rep < 4; rep++) {
        int o = tid + rep * 256;
        float acc = t_b[o];
        const float* w = t_w + (long long)o * TDIM_;
        for (int j = 0; j < TDIM_; j += 4) {
            float4 wv = *reinterpret_cast<const float4*>(w + j);
            acc += te[j] * wv.x + te[j+1] * wv.y + te[j+2] * wv.z + te[j+3] * wv.w;
        }
        float sig = 1.0f / (1.0f + __expf(-acc));
        g_cs[b * HID_ + o] = acc * sig;
    }
}

// ---------------- all adaLN projections ----------------
__global__ void k_ada(const float* __restrict__ ada_w,
                      const float* __restrict__ ada_b,
                      const float* __restrict__ fada_w,
                      const float* __restrict__ fada_b)
{
    int d = blockIdx.x;
    int chunk = blockIdx.y;
    int tid = threadIdx.x;
    __shared__ float css[B_][HID_];
    for (int i = tid; i < B_ * HID_; i += 256)
        css[i >> 10][i & 1023] = g_cs[i];
    __syncthreads();

    int cnt = (d < DEPTH_) ? 6 * HID_ : 2 * HID_;
    int o = chunk * 256 + tid;
    if (o >= cnt) return;

    const float* W = (d < DEPTH_) ? ada_w + ((long long)d * 6 * HID_ + o) * HID_
                                  : fada_w + (long long)o * HID_;
    float bia = (d < DEPTH_) ? ada_b[d * 6 * HID_ + o] : fada_b[o];
    float acc[B_];
#pragma unroll
    for (int b = 0; b < B_; b++) acc[b] = bia;

    for (int j = 0; j < HID_; j += 4) {
        float4 wv = *reinterpret_cast<const float4*>(W + j);
#pragma unroll
        for (int b = 0; b < B_; b++) {
            acc[b] += css[b][j] * wv.x + css[b][j+1] * wv.y
                    + css[b][j+2] * wv.z + css[b][j+3] * wv.w;
        }
    }
#pragma unroll
    for (int b = 0; b < B_; b++) {
        if (d < DEPTH_) g_ada[((long long)(d * B_ + b)) * 6 * HID_ + o] = acc[b];
        else            g_fada[b * 2 * HID_ + o] = acc[b];
    }
}

// ---------------- patchify + bias + pos embed ----------------
__global__ void k_patch(const float* __restrict__ x,
                        const float* __restrict__ patch_w,
                        const float* __restrict__ patch_b)
{
    int tok = blockIdx.x;
    int b = tok >> 10;
    int n = tok & 1023;
    int hp = n >> 4;
    int wp = n & 15;
    int tid = threadIdx.x;
    __shared__ float xs[32];
    if (tid < 32) {
        int c = tid >> 4;
        int r = (tid >> 2) & 3;
        int q = tid & 3;
        xs[c * 16 + r * 4 + q] = x[((long long)(b * C_ + c) * H_ + hp * 4 + r) * W_ + wp * 4 + q];
    }
    __syncthreads();
    const float LOG1E4 = logf(10000.0f);
#pragma unroll
    for (int rep = 0; rep < 4; rep++) {
        int o = tid + rep * 256;
        float acc = patch_b[o];
        const float4* w4 = reinterpret_cast<const float4*>(patch_w + o * 32);
#pragma unroll
        for (int i = 0; i < 8; i++) {
            float4 wv = w4[i];
            acc += xs[i*4+0] * wv.x + xs[i*4+1] * wv.y + xs[i*4+2] * wv.z + xs[i*4+3] * wv.w;
        }
        int j = o & 255;
        int sec = o >> 8;
        float omega = __expf(-LOG1E4 * (float)j / 256.0f);
        float p = (sec < 2) ? (float)wp : (float)hp;
        float a = p * omega;
        float pos = (sec & 1) ? cosf(a) : sinf(a);
        g_h[(long long)tok * HID_ + o] = acc + pos;
    }
}

// ---------------- RMSNorm + modulate -> fp16 ----------------
__global__ void k_rmsmod(const float* __restrict__ in, u16* __restrict__ out,
                         const float* __restrict__ nw,
                         const float* __restrict__ ada, int ada_stride,
                         int shift_off, int scale_off)
{
    int tok = blockIdx.x;
    int b = tok >> 10;
    int tid = threadIdx.x;
    const float* row = in + (long long)tok * HID_;
    float v[4];
    float s = 0.0f;
#pragma unroll
    for (int i = 0; i < 4; i++) { v[i] = row[tid + i * 256]; s += v[i] * v[i]; }
    __shared__ float red[256];
    red[tid] = s; __syncthreads();
    for (int o = 128; o > 0; o >>= 1) { if (tid < o) red[tid] += red[tid + o]; __syncthreads(); }
    float rs = rsqrtf(red[0] / (float)HID_ + EPS_);
    const float* ar = ada + (long long)b * ada_stride;
    u16* orow = out + (long long)tok * HID_;
#pragma unroll
    for (int i = 0; i < 4; i++) {
        int cidx = tid + i * 256;
        orow[cidx] = h16(v[i] * rs * nw[cidx] * (1.0f + ar[scale_off + cidx]) + ar[shift_off + cidx]);
    }
}

// ---------------- per-head qk RMSNorm + RoPE + v transpose (fp16 in) ----------------
__global__ void k_rope(const float* __restrict__ qn, const float* __restrict__ kn)
{
    int tok = blockIdx.x;
    int b = tok >> 10;
    int n = tok & 1023;
    int tid = threadIdx.x;
    int h = tid >> 4;
    int l = tid & 15;
    int d0 = l * 4;
    const u16* row = g_qkv + (long long)tok * 3 * HID_;
    uint2 qr = *reinterpret_cast<const uint2*>(row + h * HD_ + d0);
    uint2 kr = *reinterpret_cast<const uint2*>(row + HID_ + h * HD_ + d0);
    uint2 vr = *reinterpret_cast<const uint2*>(row + 2 * HID_ + h * HD_ + d0);
    float2 q01 = h2f(qr.x), q23 = h2f(qr.y);
    float2 k01 = h2f(kr.x), k23 = h2f(kr.y);
    float4 q = make_float4(q01.x, q01.y, q23.x, q23.y);
    float4 k = make_float4(k01.x, k01.y, k23.x, k23.y);

    float sq = q.x*q.x + q.y*q.y + q.z*q.z + q.w*q.w;
    float sk = k.x*k.x + k.y*k.y + k.z*k.z + k.w*k.w;
#pragma unroll
    for (int o = 1; o < 16; o <<= 1) {
        sq += __shfl_xor_sync(0xffffffffu, sq, o);
        sk += __shfl_xor_sync(0xffffffffu, sk, o);
    }
    float rq = rsqrtf(sq / (float)HD_ + EPS_);
    float rk = rsqrtf(sk / (float)HD_ + EPS_);
    q.x *= rq * qn[d0+0]; q.y *= rq * qn[d0+1]; q.z *= rq * qn[d0+2]; q.w *= rq * qn[d0+3];
    k.x *= rk * kn[d0+0]; k.y *= rk * kn[d0+1]; k.z *= rk * kn[d0+2]; k.w *= rk * kn[d0+3];

    const float LOG1E4 = logf(10000.0f);
    float hpos = (float)(n >> 4);
    float wpos = (float)(n & 15);
#pragma unroll
    for (int pr = 0; pr < 2; pr++) {
        int dp = d0 + pr * 2;
        int jj; float pos;
        if (dp < 32) { jj = dp;      pos = hpos; }
        else         { jj = dp - 32; pos = wpos; }
        float freq = __expf(-LOG1E4 * (float)jj / 32.0f);
        float ang = pos * freq;
        float c = cosf(ang), s = sinf(ang);
        float qx0 = (pr == 0) ? q.x : q.z;
        float qx1 = (pr == 0) ? q.y : q.w;
        float kx0 = (pr == 0) ? k.x : k.z;
        float kx1 = (pr == 0) ? k.y : k.w;
        float qy0 = qx0 * c - qx1 * s;
        float qy1 = qx1 * c + qx0 * s;
        float ky0 = kx0 * c - kx1 * s;
        float ky1 = kx1 * c + kx0 * s;
        if (pr == 0) { q.x = qy0; q.y = qy1; k.x = ky0; k.y = ky1; }
        else         { q.z = qy0; q.w = qy1; k.z = ky0; k.w = ky1; }
    }

    long long qbase = ((long long)(b * NH_ + h) * N_ + n) * HD_ + d0;
    *reinterpret_cast<float4*>(g_q + qbase) = q;
    uint2 kp; kp.x = f2h2(k.x, k.y); kp.y = f2h2(k.z, k.w);
    *reinterpret_cast<uint2*>(g_k + qbase) = kp;
    long long vb = (long long)(b * NH_ + h) * HD_;
    g_vT[(vb + d0 + 0) * N_ + n] = (u16)(vr.x & 0xffff);
    g_vT[(vb + d0 + 1) * N_ + n] = (u16)(vr.x >> 16);
    g_vT[(vb + d0 + 2) * N_ + n] = (u16)(vr.y & 0xffff);
    g_vT[(vb + d0 + 3) * N_ + n] = (u16)(vr.y >> 16);
}

// ---------------- unpatchify ----------------
__global__ void k_unpatch(float* __restrict__ out)
{
    int idx = blockIdx.x * 256 + threadIdx.x;
    if (idx >= B_ * C_ * H_ * W_) return;
    int ww = idx % W_;
    int tmp = idx / W_;
    int hh = tmp % H_;
    int tmp2 = tmp / H_;
    int c = tmp2 % C_;
    int b = tmp2 / C_;
    int hp = hh >> 2, p = hh & 3;
    int wp = ww >> 2, q = ww & 3;
    out[idx] = g_fin[((long long)(b * N_ + hp * WP_ + wp)) * OUT_ + p * (PW_ * C_) + q * C_ + c];
}

// ---------------- host orchestration ----------------
extern "C" void kernel_launch(void* const* d_in, const int* in_sizes, int n_in,
                              void* d_out, int out_size)
{
    const float* x       = (const float*)d_in[0];
    const float* t       = (const float*)d_in[1];
    const float* patch_w = (const float*)d_in[2];
    const float* patch_b = (const float*)d_in[3];
    const float* t_w     = (const float*)d_in[4];
    const float* t_b     = (const float*)d_in[5];
    const float* norm1_w = (const float*)d_in[6];
    const float* qkv_w   = (const float*)d_in[7];
    const float* qkv_b   = (const float*)d_in[8];
    const float* qn_w    = (const float*)d_in[9];
    const float* kn_w    = (const float*)d_in[10];
    const float* proj_w  = (const float*)d_in[11];
    const float* proj_b  = (const float*)d_in[12];
    const float* norm2_w = (const float*)d_in[13];
    const float* w12_w   = (const float*)d_in[14];
    const float* w12_b   = (const float*)d_in[15];
    const float* w3_w    = (const float*)d_in[16];
    const float* w3_b    = (const float*)d_in[17];
    const float* ada_w   = (const float*)d_in[18];
    const float* ada_b   = (const float*)d_in[19];
    const float* fnorm_w = (const float*)d_in[20];
    const float* flin_w  = (const float*)d_in[21];
    const float* flin_b  = (const float*)d_in[22];
    const float* fada_w  = (const float*)d_in[23];
    const float* fada_b  = (const float*)d_in[24];
    float* out = (float*)d_out;

    cudaFuncSetAttribute(k_flash, cudaFuncAttributeMaxDynamicSharedMemorySize, FLASH_SMEM);

    float *p_h, *p_q, *p_fin, *p_ada, *p_fada;
    u16 *p_hn, *p_qkv, *p_k, *p_vT, *p_ao, *p_ffn, *p_wq, *p_wp, *p_w12, *p_w3, *p_wf;
    cudaGetSymbolAddress((void**)&p_h,   g_h);
    cudaGetSymbolAddress((void**)&p_hn,  g_hn);
    cudaGetSymbolAddress((void**)&p_qkv, g_qkv);
    cudaGetSymbolAddress((void**)&p_q,   g_q);
    cudaGetSymbolAddress((void**)&p_k,   g_k);
    cudaGetSymbolAddress((void**)&p_vT,  g_vT);
    cudaGetSymbolAddress((void**)&p_ao,  g_ao);
    cudaGetSymbolAddress((void**)&p_ffn, g_ffn);
    cudaGetSymbolAddress((void**)&p_fin, g_fin);
    cudaGetSymbolAddress((void**)&p_ada, g_ada);
    cudaGetSymbolAddress((void**)&p_fada, g_fada);
    cudaGetSymbolAddress((void**)&p_wq,  g_wq);
    cudaGetSymbolAddress((void**)&p_wp,  g_wp);
    cudaGetSymbolAddress((void**)&p_w12, g_w12);
    cudaGetSymbolAddress((void**)&p_w3,  g_w3);
    cudaGetSymbolAddress((void**)&p_wf,  g_wf);

    auto cvt = [](const float* src, u16* dst, int srcK, int dstK,
                  int srcRows, int dstRows, long long mats) {
        long long total = mats * dstRows * dstK;
        k_wcvt<<<(unsigned)((total + 255) / 256), 256>>>(src, dst, srcK, dstK,
                                                         srcRows, dstRows, total);
    };

    auto gemm = [](const u16* A, int lda, const u16* Wh, int ldw,
                   void* C, int ldc, int M, int Nout, int K,
                   const float* bias, const float* res,
                   const float* gate, int gstride, int mode) {
        dim3 grid((Nout + 127) / 128, M / 128);
        k_gemm_h1<<<grid, 256>>>(A, lda, Wh, ldw, C, ldc, M, Nout, K,
                                 bias, res, gate, gstride, mode);
    };

    // setup
    k_timestep<<<B_, 256>>>(t, t_w, t_b);
    k_ada<<<dim3(DEPTH_ + 1, 24), 256>>>(ada_w, ada_b, fada_w, fada_b);
    cvt(qkv_w, p_wq, HID_, HID_, 3 * HID_, 3 * HID_, DEPTH_);
    cvt(proj_w, p_wp, HID_, HID_, HID_, HID_, DEPTH_);
    {
        long long tot = (long long)DEPTH_ * NW12_ * HID_;
        k_wcvt12<<<(unsigned)((tot + 255) / 256), 256>>>(w12_w, p_w12);
    }
    cvt(w3_w, p_w3, FFN_, FFNP_, HID_, HID_, DEPTH_);
    cvt(flin_w, p_wf, HID_, HID_, OUT_, OUTP_, 1);
    k_patch<<<T_, 256>>>(x, patch_w, patch_b);

    for (int d = 0; d < DEPTH_; d++) {
        const float* adab = p_ada + (long long)d * B_ * 6 * HID_;

        // norm1 + modulate -> fp16
        k_rmsmod<<<T_, 256>>>(p_h, p_hn, norm1_w + d * HID_, adab, 6 * HID_, 0, HID_);

        // qkv -> fp16
        gemm(p_hn, HID_, p_wq + (long long)d * 3 * HID_ * HID_, HID_,
             p_qkv, 3 * HID_, T_, 3 * HID_, HID_,
             qkv_b + d * 3 * HID_, nullptr, nullptr, 0, 3);

        // qk-norm + rope + v transpose
        k_rope<<<T_, 256>>>(qn_w + d * HD_, kn_w + d * HD_);

        // fused flash attention -> g_ao (fp16)
        k_flash<<<dim3(N_ / 128, B_ * NH_), 256, FLASH_SMEM>>>(p_q, p_k, p_vT, p_ao);

        // proj + gated residual (gm)
        gemm(p_ao, HID_, p_wp + (long long)d * HID_ * HID_, HID_,
             p_h, HID_, T_, HID_, HID_,
             proj_b + d * HID_, p_h, adab + 2 * HID_, 6 * HID_, 1);

        // norm2 + modulate -> fp16
        k_rmsmod<<<T_, 256>>>(p_h, p_hn, norm2_w + d * HID_, adab, 6 * HID_, 3 * HID_, 4 * HID_);

        // w12 GEMM with fused swiglu -> g_ffn (fp16)
        gemm(p_hn, HID_, p_w12 + (long long)d * NW12_ * HID_, HID_,
             p_ffn, FFNP_, T_, NW12_, HID_,
             w12_b + (long long)d * 2 * FFN_, nullptr, nullptr, 0, 2);

        // w3 + gated residual (gp)
        gemm(p_ffn, FFNP_, p_w3 + (long long)d * HID_ * FFNP_, FFNP_,
             p_h, HID_, T_, HID_, FFNP_,
             w3_b + d * HID_, p_h, adab + 5 * HID_, 6 * HID_, 1);
    }

    // final norm + modulate -> fp16
    k_rmsmod<<<T_, 256>>>(p_h, p_hn, fnorm_w, p_fada, 2 * HID_, 0, HID_);

    // final linear
    gemm(p_hn, HID_, p_wf, HID_,
         p_fin, OUT_, T_, OUT_, HID_,
         flin_b, nullptr, nullptr, 0, 0);

    k_unpatch<<<(B_ * C_ * H_ * W_ + 255) / 256, 256>>>(out);
}